// round 4
// baseline (speedup 1.0000x reference)
#include <cuda_runtime.h>
#include <math.h>
#include <stdint.h>

#define HEADS   12
#define DH      64
#define SEQ     2048
#define BATCH   4
#define DMODEL  768
#define QKVW    2304      // 3 * 768
#define SCALE   0.125f    // 64^-0.5

// Scratch (device globals; no allocations allowed)
__device__ float g_qkv[(size_t)BATCH * SEQ * QKVW];    // 75.5 MB
__device__ float g_attn[(size_t)BATCH * SEQ * DMODEL]; // 25 MB

// ---------------------------------------------------------------------------
// tf32 helpers
// ---------------------------------------------------------------------------
__device__ __forceinline__ uint32_t f2tf32(float f) {
    uint32_t u;
    asm("cvt.rna.tf32.f32 %0, %1;" : "=r"(u) : "f"(f));
    return u;
}

// D = A(16x8) @ B(8x8) + D, tf32 inputs, fp32 accum.
__device__ __forceinline__ void mma_tf32(float c[4],
                                         uint32_t a0, uint32_t a1,
                                         uint32_t a2, uint32_t a3,
                                         uint32_t b0, uint32_t b1) {
    asm volatile(
        "mma.sync.aligned.m16n8k8.row.col.f32.tf32.tf32.f32 "
        "{%0,%1,%2,%3}, {%4,%5,%6,%7}, {%8,%9}, {%0,%1,%2,%3};\n"
        : "+f"(c[0]), "+f"(c[1]), "+f"(c[2]), "+f"(c[3])
        : "r"(a0), "r"(a1), "r"(a2), "r"(a3), "r"(b0), "r"(b1));
}

// ---------------------------------------------------------------------------
// GEMM (tf32 tensor cores): C[M,N] = A[M,K] @ B[K,N] (+ bias), row-major.
// 128x128 block tile, BK=32, 256 threads = 8 warps (2x4), warp tile 64x32.
// 2-stage smem double buffer: one __syncthreads per k-step; global prefetch
// overlaps the MMA stage; tf32 cvt.rna on the smem-store path.
// ---------------------------------------------------------------------------
#define BM 128
#define BN 128
#define BK 32
#define AS_W (BK + 4)     // 36
#define BS_W (BN + 4)     // 132
#define GEMM_SMEM_WORDS (2 * BM * AS_W + 2 * BK * BS_W)
#define GEMM_SMEM_BYTES (GEMM_SMEM_WORDS * 4)

__global__ __launch_bounds__(256)
void gemm_tf32(const float* __restrict__ A, const float* __restrict__ B,
               const float* __restrict__ bias, float* __restrict__ C,
               int M, int N, int K) {
    extern __shared__ uint32_t gsm[];
    uint32_t* AsB[2] = { gsm, gsm + BM * AS_W };
    uint32_t* BsB[2] = { gsm + 2 * BM * AS_W, gsm + 2 * BM * AS_W + BK * BS_W };

    int tid  = threadIdx.x;
    int lane = tid & 31, wid = tid >> 5;
    int wm = (wid >> 2) * 64;    // warp m offset (0|64)
    int wn = (wid & 3) * 32;     // warp n offset (0..96)
    int g  = lane >> 2, q = lane & 3;

    int row0 = blockIdx.y * BM, col0 = blockIdx.x * BN;

    int aRow = tid >> 3, aCol = (tid & 7) << 2;    // A: 128x32, 4 f4/thr
    int bRow = tid >> 5, bCol = (tid & 31) << 2;   // B: 32x128, 4 f4/thr

    float acc[4][4][4] = {};
    float4 pa[4], pb[4];

    // prime stage 0
    #pragma unroll
    for (int i = 0; i < 4; i++)
        pa[i] = *(const float4*)(A + (size_t)(row0 + aRow + 32 * i) * K + aCol);
    #pragma unroll
    for (int i = 0; i < 4; i++)
        pb[i] = *(const float4*)(B + (size_t)(bRow + 8 * i) * N + col0 + bCol);
    #pragma unroll
    for (int i = 0; i < 4; i++)
        *(uint4*)&AsB[0][(aRow + 32 * i) * AS_W + aCol] =
            make_uint4(f2tf32(pa[i].x), f2tf32(pa[i].y), f2tf32(pa[i].z), f2tf32(pa[i].w));
    #pragma unroll
    for (int i = 0; i < 4; i++)
        *(uint4*)&BsB[0][(bRow + 8 * i) * BS_W + bCol] =
            make_uint4(f2tf32(pb[i].x), f2tf32(pb[i].y), f2tf32(pb[i].z), f2tf32(pb[i].w));
    __syncthreads();

    int buf = 0;
    for (int k0 = 0; k0 < K; k0 += BK) {
        int kn = k0 + BK;
        bool more = kn < K;
        if (more) {
            #pragma unroll
            for (int i = 0; i < 4; i++)
                pa[i] = *(const float4*)(A + (size_t)(row0 + aRow + 32 * i) * K + kn + aCol);
            #pragma unroll
            for (int i = 0; i < 4; i++)
                pb[i] = *(const float4*)(B + (size_t)(kn + bRow + 8 * i) * N + col0 + bCol);
        }

        const uint32_t* As = AsB[buf];
        const uint32_t* Bs = BsB[buf];
        #pragma unroll
        for (int ks = 0; ks < BK / 8; ks++) {
            int kk = ks * 8;
            uint32_t af[4][4];
            #pragma unroll
            for (int mt = 0; mt < 4; mt++) {
                int r = wm + mt * 16;
                af[mt][0] = As[(r + g    ) * AS_W + kk + q    ];
                af[mt][1] = As[(r + g + 8) * AS_W + kk + q    ];
                af[mt][2] = As[(r + g    ) * AS_W + kk + q + 4];
                af[mt][3] = As[(r + g + 8) * AS_W + kk + q + 4];
            }
            uint32_t bf[4][2];
            #pragma unroll
            for (int nt = 0; nt < 4; nt++) {
                int c = wn + nt * 8 + g;
                bf[nt][0] = Bs[(kk + q    ) * BS_W + c];
                bf[nt][1] = Bs[(kk + q + 4) * BS_W + c];
            }
            #pragma unroll
            for (int mt = 0; mt < 4; mt++)
                #pragma unroll
                for (int nt = 0; nt < 4; nt++)
                    mma_tf32(acc[mt][nt], af[mt][0], af[mt][1], af[mt][2], af[mt][3],
                             bf[nt][0], bf[nt][1]);
        }

        if (more) {
            uint32_t* An = AsB[buf ^ 1];
            uint32_t* Bn = BsB[buf ^ 1];
            #pragma unroll
            for (int i = 0; i < 4; i++)
                *(uint4*)&An[(aRow + 32 * i) * AS_W + aCol] =
                    make_uint4(f2tf32(pa[i].x), f2tf32(pa[i].y), f2tf32(pa[i].z), f2tf32(pa[i].w));
            #pragma unroll
            for (int i = 0; i < 4; i++)
                *(uint4*)&Bn[(bRow + 8 * i) * BS_W + bCol] =
                    make_uint4(f2tf32(pb[i].x), f2tf32(pb[i].y), f2tf32(pb[i].z), f2tf32(pb[i].w));
            __syncthreads();
            buf ^= 1;
        }
    }

    // epilogue
    #pragma unroll
    for (int mt = 0; mt < 4; mt++) {
        int r = row0 + wm + mt * 16 + g;
        #pragma unroll
        for (int nt = 0; nt < 4; nt++) {
            int c = col0 + wn + nt * 8 + 2 * q;
            float bx = 0.f, by = 0.f;
            if (bias) { bx = bias[c]; by = bias[c + 1]; }
            *(float2*)(C + (size_t)r * N + c) =
                make_float2(acc[mt][nt][0] + bx, acc[mt][nt][1] + by);
            *(float2*)(C + (size_t)(r + 8) * N + c) =
                make_float2(acc[mt][nt][2] + bx, acc[mt][nt][3] + by);
        }
    }
}

// ---------------------------------------------------------------------------
// Flash attention (tf32 tensor cores): block = (b, h, 128-row Q tile),
// 256 threads = 8 warps, each warp owns a 16-row strip. Online softmax on
// C-fragments with quad-lane shfl reductions; P staged via warp-private smem
// rows (syncwarp only). 104 KB smem -> 2 CTA/SM, 16 warps/SM.
// ---------------------------------------------------------------------------
#define QT  128
#define KT  64
#define FDH 68   // 64 + 4 pad
#define FLASH_SMEM_BYTES ((2 * QT + 2 * KT) * FDH * 4)

__global__ __launch_bounds__(256)
void flash_tf32(const float* __restrict__ qkv, float* __restrict__ out) {
    extern __shared__ float sm[];
    float* Qs = sm;                          // [QT][FDH] tf32 bits (Q*SCALE)
    float* Ks = sm + QT * FDH;               // [KT][FDH]
    float* Vs = sm + (QT + KT) * FDH;        // [KT][FDH]
    float* Ps = sm + (QT + 2 * KT) * FDH;    // [QT][FDH]

    int b  = blockIdx.z, h = blockIdx.y;
    int q0 = blockIdx.x * QT;
    int tid = threadIdx.x;
    int lane = tid & 31, wid = tid >> 5;
    int g = lane >> 2, qd = lane & 3;
    int m0 = wid * 16;

    const float* base = qkv + (size_t)b * SEQ * QKVW;
    int hc = h * DH;

    // Q tile [128][64], pre-scaled by 2^-3 (exact), tf32-rounded
    #pragma unroll
    for (int i = 0; i < 8; i++) {
        int f = tid + i * 256;
        int r = f >> 4, c = (f & 15) << 2;
        float4 v = *(const float4*)(base + (size_t)(q0 + r) * QKVW + hc + c);
        *(uint4*)&Qs[r * FDH + c] =
            make_uint4(f2tf32(v.x * SCALE), f2tf32(v.y * SCALE),
                       f2tf32(v.z * SCALE), f2tf32(v.w * SCALE));
    }

    float o[8][4] = {};
    float mr0 = -INFINITY, mr1 = -INFINITY, l0 = 0.f, l1 = 0.f;
    __syncthreads();

    for (int kt = 0; kt < SEQ / KT; kt++) {
        int k0 = kt * KT;
        #pragma unroll
        for (int i = 0; i < 4; i++) {
            int f = tid + i * 256;
            int r = f >> 4, c = (f & 15) << 2;
            const float* src = base + (size_t)(k0 + r) * QKVW + hc + c;
            float4 kv = *(const float4*)(src + DMODEL);
            float4 vv = *(const float4*)(src + 2 * DMODEL);
            *(uint4*)&Ks[r * FDH + c] =
                make_uint4(f2tf32(kv.x), f2tf32(kv.y), f2tf32(kv.z), f2tf32(kv.w));
            *(uint4*)&Vs[r * FDH + c] =
                make_uint4(f2tf32(vv.x), f2tf32(vv.y), f2tf32(vv.z), f2tf32(vv.w));
        }
        __syncthreads();

        // S(16x64) = Qstrip @ K^T  (scale folded into Q)
        float s[8][4] = {};
        #pragma unroll
        for (int ks = 0; ks < 8; ks++) {
            int kk = ks * 8;
            uint32_t a0 = __float_as_uint(Qs[(m0 + g    ) * FDH + kk + qd    ]);
            uint32_t a1 = __float_as_uint(Qs[(m0 + g + 8) * FDH + kk + qd    ]);
            uint32_t a2 = __float_as_uint(Qs[(m0 + g    ) * FDH + kk + qd + 4]);
            uint32_t a3 = __float_as_uint(Qs[(m0 + g + 8) * FDH + kk + qd + 4]);
            #pragma unroll
            for (int nt = 0; nt < 8; nt++) {
                uint32_t b0 = __float_as_uint(Ks[(nt * 8 + g) * FDH + kk + qd    ]);
                uint32_t b1 = __float_as_uint(Ks[(nt * 8 + g) * FDH + kk + qd + 4]);
                mma_tf32(s[nt], a0, a1, a2, a3, b0, b1);
            }
        }

        // online softmax: rows (m0+g) and (m0+g+8); 4 lanes per row
        float mx0 = -INFINITY, mx1 = -INFINITY;
        #pragma unroll
        for (int nt = 0; nt < 8; nt++) {
            mx0 = fmaxf(mx0, fmaxf(s[nt][0], s[nt][1]));
            mx1 = fmaxf(mx1, fmaxf(s[nt][2], s[nt][3]));
        }
        #pragma unroll
        for (int w = 1; w < 4; w <<= 1) {
            mx0 = fmaxf(mx0, __shfl_xor_sync(0xffffffffu, mx0, w));
            mx1 = fmaxf(mx1, __shfl_xor_sync(0xffffffffu, mx1, w));
        }
        float mn0 = fmaxf(mr0, mx0), mn1 = fmaxf(mr1, mx1);
        float al0 = __expf(mr0 - mn0), al1 = __expf(mr1 - mn1);
        mr0 = mn0; mr1 = mn1;

        float sum0 = 0.f, sum1 = 0.f;
        #pragma unroll
        for (int nt = 0; nt < 8; nt++) {
            s[nt][0] = __expf(s[nt][0] - mn0); sum0 += s[nt][0];
            s[nt][1] = __expf(s[nt][1] - mn0); sum0 += s[nt][1];
            s[nt][2] = __expf(s[nt][2] - mn1); sum1 += s[nt][2];
            s[nt][3] = __expf(s[nt][3] - mn1); sum1 += s[nt][3];
        }
        #pragma unroll
        for (int w = 1; w < 4; w <<= 1) {
            sum0 += __shfl_xor_sync(0xffffffffu, sum0, w);
            sum1 += __shfl_xor_sync(0xffffffffu, sum1, w);
        }
        l0 = l0 * al0 + sum0;
        l1 = l1 * al1 + sum1;

        // stage P (C-frag -> smem, tf32); rows are warp-private
        #pragma unroll
        for (int nt = 0; nt < 8; nt++) {
            int c = nt * 8 + 2 * qd;
            Ps[(m0 + g    ) * FDH + c    ] = __uint_as_float(f2tf32(s[nt][0]));
            Ps[(m0 + g    ) * FDH + c + 1] = __uint_as_float(f2tf32(s[nt][1]));
            Ps[(m0 + g + 8) * FDH + c    ] = __uint_as_float(f2tf32(s[nt][2]));
            Ps[(m0 + g + 8) * FDH + c + 1] = __uint_as_float(f2tf32(s[nt][3]));
        }
        __syncwarp();

        // O = O*alpha + P @ V
        #pragma unroll
        for (int nt = 0; nt < 8; nt++) {
            o[nt][0] *= al0; o[nt][1] *= al0;
            o[nt][2] *= al1; o[nt][3] *= al1;
        }
        #pragma unroll
        for (int ks = 0; ks < 8; ks++) {
            int kk = ks * 8;
            uint32_t a0 = __float_as_uint(Ps[(m0 + g    ) * FDH + kk + qd    ]);
            uint32_t a1 = __float_as_uint(Ps[(m0 + g + 8) * FDH + kk + qd    ]);
            uint32_t a2 = __float_as_uint(Ps[(m0 + g    ) * FDH + kk + qd + 4]);
            uint32_t a3 = __float_as_uint(Ps[(m0 + g + 8) * FDH + kk + qd + 4]);
            #pragma unroll
            for (int nt = 0; nt < 8; nt++) {
                uint32_t b0 = __float_as_uint(Vs[(kk + qd    ) * FDH + nt * 8 + g]);
                uint32_t b1 = __float_as_uint(Vs[(kk + qd + 4) * FDH + nt * 8 + g]);
                mma_tf32(o[nt], a0, a1, a2, a3, b0, b1);
            }
        }
        __syncthreads();   // Ks/Vs fully consumed before next tile's stores
    }

    // normalize + write 'b n (h d)'
    float inv0 = 1.f / l0, inv1 = 1.f / l1;
    #pragma unroll
    for (int nt = 0; nt < 8; nt++) {
        int r = q0 + m0 + g;
        int c = hc + nt * 8 + 2 * qd;
        *(float2*)(out + (size_t)((size_t)b * SEQ + r) * DMODEL + c) =
            make_float2(o[nt][0] * inv0, o[nt][1] * inv0);
        *(float2*)(out + (size_t)((size_t)b * SEQ + r + 8) * DMODEL + c) =
            make_float2(o[nt][2] * inv1, o[nt][3] * inv1);
    }
}

// ---------------------------------------------------------------------------
extern "C" void kernel_launch(void* const* d_in, const int* in_sizes, int n_in,
                              void* d_out, int out_size) {
    const float* x     = (const float*)d_in[0];   // [4,2048,768]
    const float* W_qkv = (const float*)d_in[1];   // [768,2304]
    const float* W_out = (const float*)d_in[2];   // [768,768]
    const float* b_out = (const float*)d_in[3];   // [768]
    float* out = (float*)d_out;                   // [4,2048,768]

    float* qkv;  cudaGetSymbolAddress((void**)&qkv,  g_qkv);
    float* attn; cudaGetSymbolAddress((void**)&attn, g_attn);

    cudaFuncSetAttribute(gemm_tf32,
                         cudaFuncAttributeMaxDynamicSharedMemorySize,
                         GEMM_SMEM_BYTES);
    cudaFuncSetAttribute(flash_tf32,
                         cudaFuncAttributeMaxDynamicSharedMemorySize,
                         FLASH_SMEM_BYTES);

    const int M = BATCH * SEQ;  // 8192

    // 1) qkv = x @ W_qkv
    gemm_tf32<<<dim3(QKVW / BN, M / BM), 256, GEMM_SMEM_BYTES>>>(
        x, W_qkv, nullptr, qkv, M, QKVW, DMODEL);

    // 2) attention per (b, h, q-tile)
    flash_tf32<<<dim3(SEQ / QT, HEADS, BATCH), 256, FLASH_SMEM_BYTES>>>(
        qkv, attn);

    // 3) out = attn @ W_out + b_out
    gemm_tf32<<<dim3(DMODEL / BN, M / BM), 256, GEMM_SMEM_BYTES>>>(
        attn, W_out, b_out, out, M, DMODEL, DMODEL);
}

// round 5
// speedup vs baseline: 1.0996x; 1.0996x over previous
#include <cuda_runtime.h>
#include <math.h>
#include <stdint.h>

#define HEADS   12
#define DH      64
#define SEQ     2048
#define BATCH   4
#define DMODEL  768
#define QKVW    2304      // 3 * 768
#define SCALE   0.125f    // 64^-0.5

// Scratch (device globals; no allocations allowed)
__device__ float g_qkv[(size_t)BATCH * SEQ * QKVW];    // 75.5 MB
__device__ float g_attn[(size_t)BATCH * SEQ * DMODEL]; // 25 MB

// ---------------------------------------------------------------------------
// tf32 / ldmatrix helpers
// ---------------------------------------------------------------------------
__device__ __forceinline__ uint32_t f2tf32(float f) {
    uint32_t u;
    asm("cvt.rna.tf32.f32 %0, %1;" : "=r"(u) : "f"(f));
    return u;
}

__device__ __forceinline__ void mma_tf32(float c[4],
                                         uint32_t a0, uint32_t a1,
                                         uint32_t a2, uint32_t a3,
                                         uint32_t b0, uint32_t b1) {
    asm volatile(
        "mma.sync.aligned.m16n8k8.row.col.f32.tf32.tf32.f32 "
        "{%0,%1,%2,%3}, {%4,%5,%6,%7}, {%8,%9}, {%0,%1,%2,%3};\n"
        : "+f"(c[0]), "+f"(c[1]), "+f"(c[2]), "+f"(c[3])
        : "r"(a0), "r"(a1), "r"(a2), "r"(a3), "r"(b0), "r"(b1));
}

// 16x16 b16 view of a 16x8 tf32 tile -> the four m16n8k8 tf32 fragments.
// Lane l supplies row (l&15), tf32-col-offset (l>>4)*4 of the tile.
__device__ __forceinline__ void ldsm_x4(uint32_t& r0, uint32_t& r1,
                                        uint32_t& r2, uint32_t& r3,
                                        uint32_t addr) {
    asm volatile(
        "ldmatrix.sync.aligned.m8n8.x4.shared.b16 {%0,%1,%2,%3}, [%4];"
        : "=r"(r0), "=r"(r1), "=r"(r2), "=r"(r3) : "r"(addr));
}

// ---------------------------------------------------------------------------
// GEMM (tf32): C[M,N] = A[M,K] @ B[K,N] (+ bias), row-major.
// 128x128 tile, BK=32, 256 threads = 8 warps, warp tile 64x32.
// Single-buffer smem (35KB -> 2 CTA/SM); A fragments via ldmatrix.x4.
// ---------------------------------------------------------------------------
#define BM 128
#define BN 128
#define BK 32
#define AS_W (BK + 4)     // 36 words: row stride mod 32 = 4 -> LDSM conflict-free
#define BS_W (BN + 4)     // 132

__global__ __launch_bounds__(256)
void gemm_tf32(const float* __restrict__ A, const float* __restrict__ B,
               const float* __restrict__ bias, float* __restrict__ C,
               int M, int N, int K) {
    __shared__ uint32_t As[BM * AS_W];
    __shared__ uint32_t Bs[BK * BS_W];

    int tid  = threadIdx.x;
    int lane = tid & 31, wid = tid >> 5;
    int wm = (wid >> 2) * 64;
    int wn = (wid & 3) * 32;
    int g  = lane >> 2, q = lane & 3;
    uint32_t lr = lane & 15, ls = (lane >> 4) * 4;

    uint32_t as_u32 = (uint32_t)__cvta_generic_to_shared(As);
    uint32_t a_off  = (wm + lr) * AS_W + ls;   // words; + mt*16*AS_W + kk

    int row0 = blockIdx.y * BM, col0 = blockIdx.x * BN;

    int aRow = tid >> 3, aCol = (tid & 7) << 2;
    int bRow = tid >> 5, bCol = (tid & 31) << 2;

    float acc[4][4][4] = {};
    float4 pa[4], pb[4];

    #pragma unroll
    for (int i = 0; i < 4; i++)
        pa[i] = *(const float4*)(A + (size_t)(row0 + aRow + 32 * i) * K + aCol);
    #pragma unroll
    for (int i = 0; i < 4; i++)
        pb[i] = *(const float4*)(B + (size_t)(bRow + 8 * i) * N + col0 + bCol);

    for (int k0 = 0; k0 < K; k0 += BK) {
        #pragma unroll
        for (int i = 0; i < 4; i++)
            *(uint4*)&As[(aRow + 32 * i) * AS_W + aCol] =
                make_uint4(f2tf32(pa[i].x), f2tf32(pa[i].y), f2tf32(pa[i].z), f2tf32(pa[i].w));
        #pragma unroll
        for (int i = 0; i < 4; i++)
            *(uint4*)&Bs[(bRow + 8 * i) * BS_W + bCol] =
                make_uint4(f2tf32(pb[i].x), f2tf32(pb[i].y), f2tf32(pb[i].z), f2tf32(pb[i].w));
        __syncthreads();

        int kn = k0 + BK;
        if (kn < K) {
            #pragma unroll
            for (int i = 0; i < 4; i++)
                pa[i] = *(const float4*)(A + (size_t)(row0 + aRow + 32 * i) * K + kn + aCol);
            #pragma unroll
            for (int i = 0; i < 4; i++)
                pb[i] = *(const float4*)(B + (size_t)(kn + bRow + 8 * i) * N + col0 + bCol);
        }

        #pragma unroll
        for (int ks = 0; ks < BK / 8; ks++) {
            int kk = ks * 8;
            uint32_t af[4][4];
            #pragma unroll
            for (int mt = 0; mt < 4; mt++)
                ldsm_x4(af[mt][0], af[mt][1], af[mt][2], af[mt][3],
                        as_u32 + 4u * (a_off + mt * 16 * AS_W + kk));
            uint32_t bf[4][2];
            #pragma unroll
            for (int nt = 0; nt < 4; nt++) {
                int c = wn + nt * 8 + g;
                bf[nt][0] = Bs[(kk + q    ) * BS_W + c];
                bf[nt][1] = Bs[(kk + q + 4) * BS_W + c];
            }
            #pragma unroll
            for (int mt = 0; mt < 4; mt++)
                #pragma unroll
                for (int nt = 0; nt < 4; nt++)
                    mma_tf32(acc[mt][nt], af[mt][0], af[mt][1], af[mt][2], af[mt][3],
                             bf[nt][0], bf[nt][1]);
        }
        __syncthreads();
    }

    #pragma unroll
    for (int mt = 0; mt < 4; mt++) {
        int r = row0 + wm + mt * 16 + g;
        #pragma unroll
        for (int nt = 0; nt < 4; nt++) {
            int c = col0 + wn + nt * 8 + 2 * q;
            float bx = 0.f, by = 0.f;
            if (bias) { bx = bias[c]; by = bias[c + 1]; }
            *(float2*)(C + (size_t)r * N + c) =
                make_float2(acc[mt][nt][0] + bx, acc[mt][nt][1] + by);
            *(float2*)(C + (size_t)(r + 8) * N + c) =
                make_float2(acc[mt][nt][2] + bx, acc[mt][nt][3] + by);
        }
    }
}

// ---------------------------------------------------------------------------
// Flash attention (tf32): block = (b, h, 128-row Q tile), 8 warps.
// All fragments via ldmatrix.x4. K stored [n][d]; V stored TRANSPOSED [d][n]
// so PV B-fragments also load with non-trans ldmatrix. Online softmax on
// C-fragments with quad shfl; P staged via warp-private smem rows.
// ---------------------------------------------------------------------------
#define QT  128
#define KT  64
#define FW  68   // row stride (words): mod 32 = 4 -> LDSM conflict-free
#define FLASH_SMEM_BYTES ((2 * QT + 2 * KT) * FW * 4)

__global__ __launch_bounds__(256)
void flash_tf32(const float* __restrict__ qkv, float* __restrict__ out) {
    extern __shared__ float sm[];
    float* Qs  = sm;                        // [QT][FW]  Q*SCALE, tf32
    float* Ks  = sm + QT * FW;              // [KT][FW]  rows = kv pos
    float* VsT = sm + (QT + KT) * FW;       // [DH][FW]  rows = d, cols = kv pos
    float* Ps  = sm + (QT + 2 * KT) * FW;   // [QT][FW]

    int b  = blockIdx.z, h = blockIdx.y;
    int q0 = blockIdx.x * QT;
    int tid = threadIdx.x;
    int lane = tid & 31, wid = tid >> 5;
    int g = lane >> 2, qd = lane & 3;
    int m0 = wid * 16;
    uint32_t lr = lane & 15, ls = (lane >> 4) * 4;

    uint32_t q_u32 = (uint32_t)__cvta_generic_to_shared(Qs);
    uint32_t k_u32 = (uint32_t)__cvta_generic_to_shared(Ks);
    uint32_t v_u32 = (uint32_t)__cvta_generic_to_shared(VsT);
    uint32_t p_u32 = (uint32_t)__cvta_generic_to_shared(Ps);

    uint32_t aoff = (m0 + lr) * FW + ls;    // A-frag tile offset (Q and P)
    uint32_t boff = lr * FW + ls;           // B-frag block base (K and V)

    const float* base = qkv + (size_t)b * SEQ * QKVW;
    int hc = h * DH;

    // Q tile [128][64], pre-scaled, tf32
    #pragma unroll
    for (int i = 0; i < 8; i++) {
        int f = tid + i * 256;
        int r = f >> 4, c = (f & 15) << 2;
        float4 v = *(const float4*)(base + (size_t)(q0 + r) * QKVW + hc + c);
        *(uint4*)&Qs[r * FW + c] =
            make_uint4(f2tf32(v.x * SCALE), f2tf32(v.y * SCALE),
                       f2tf32(v.z * SCALE), f2tf32(v.w * SCALE));
    }

    float o[8][4] = {};
    float mr0 = -INFINITY, mr1 = -INFINITY, l0 = 0.f, l1 = 0.f;
    __syncthreads();

    for (int kt = 0; kt < SEQ / KT; kt++) {
        int k0 = kt * KT;
        #pragma unroll
        for (int i = 0; i < 4; i++) {
            int f = tid + i * 256;
            int r = f >> 4, c = (f & 15) << 2;   // r = kv pos, c = d
            const float* src = base + (size_t)(k0 + r) * QKVW + hc + c;
            float4 kv = *(const float4*)(src + DMODEL);
            float4 vv = *(const float4*)(src + 2 * DMODEL);
            *(uint4*)&Ks[r * FW + c] =
                make_uint4(f2tf32(kv.x), f2tf32(kv.y), f2tf32(kv.z), f2tf32(kv.w));
            VsT[(c + 0) * FW + r] = __uint_as_float(f2tf32(vv.x));
            VsT[(c + 1) * FW + r] = __uint_as_float(f2tf32(vv.y));
            VsT[(c + 2) * FW + r] = __uint_as_float(f2tf32(vv.z));
            VsT[(c + 3) * FW + r] = __uint_as_float(f2tf32(vv.w));
        }
        __syncthreads();

        // S(16x64) = Qstrip @ K^T
        float s[8][4] = {};
        #pragma unroll
        for (int ks = 0; ks < 8; ks++) {
            int kk = ks * 8;
            uint32_t a0, a1, a2, a3;
            ldsm_x4(a0, a1, a2, a3, q_u32 + 4u * (aoff + kk));
            #pragma unroll
            for (int nt2 = 0; nt2 < 4; nt2++) {
                uint32_t b0, b1, b2, b3;   // b0/b2: nt=2*nt2 ; b1/b3: nt=2*nt2+1
                ldsm_x4(b0, b1, b2, b3,
                        k_u32 + 4u * (boff + nt2 * 16 * FW + kk));
                mma_tf32(s[2 * nt2    ], a0, a1, a2, a3, b0, b2);
                mma_tf32(s[2 * nt2 + 1], a0, a1, a2, a3, b1, b3);
            }
        }

        // online softmax: rows (m0+g), (m0+g+8); 4 lanes per row
        float mx0 = -INFINITY, mx1 = -INFINITY;
        #pragma unroll
        for (int nt = 0; nt < 8; nt++) {
            mx0 = fmaxf(mx0, fmaxf(s[nt][0], s[nt][1]));
            mx1 = fmaxf(mx1, fmaxf(s[nt][2], s[nt][3]));
        }
        #pragma unroll
        for (int w = 1; w < 4; w <<= 1) {
            mx0 = fmaxf(mx0, __shfl_xor_sync(0xffffffffu, mx0, w));
            mx1 = fmaxf(mx1, __shfl_xor_sync(0xffffffffu, mx1, w));
        }
        float mn0 = fmaxf(mr0, mx0), mn1 = fmaxf(mr1, mx1);
        float al0 = __expf(mr0 - mn0), al1 = __expf(mr1 - mn1);
        mr0 = mn0; mr1 = mn1;

        float sum0 = 0.f, sum1 = 0.f;
        #pragma unroll
        for (int nt = 0; nt < 8; nt++) {
            s[nt][0] = __expf(s[nt][0] - mn0); sum0 += s[nt][0];
            s[nt][1] = __expf(s[nt][1] - mn0); sum0 += s[nt][1];
            s[nt][2] = __expf(s[nt][2] - mn1); sum1 += s[nt][2];
            s[nt][3] = __expf(s[nt][3] - mn1); sum1 += s[nt][3];
        }
        #pragma unroll
        for (int w = 1; w < 4; w <<= 1) {
            sum0 += __shfl_xor_sync(0xffffffffu, sum0, w);
            sum1 += __shfl_xor_sync(0xffffffffu, sum1, w);
        }
        l0 = l0 * al0 + sum0;
        l1 = l1 * al1 + sum1;

        // stage P (C-frag -> smem, tf32); rows warp-private
        #pragma unroll
        for (int nt = 0; nt < 8; nt++) {
            int c = nt * 8 + 2 * qd;
            Ps[(m0 + g    ) * FW + c    ] = __uint_as_float(f2tf32(s[nt][0]));
            Ps[(m0 + g    ) * FW + c + 1] = __uint_as_float(f2tf32(s[nt][1]));
            Ps[(m0 + g + 8) * FW + c    ] = __uint_as_float(f2tf32(s[nt][2]));
            Ps[(m0 + g + 8) * FW + c + 1] = __uint_as_float(f2tf32(s[nt][3]));
        }
        __syncwarp();

        // O = O*alpha + P @ V
        #pragma unroll
        for (int nt = 0; nt < 8; nt++) {
            o[nt][0] *= al0; o[nt][1] *= al0;
            o[nt][2] *= al1; o[nt][3] *= al1;
        }
        #pragma unroll
        for (int ks = 0; ks < 8; ks++) {
            int kk = ks * 8;
            uint32_t a0, a1, a2, a3;
            ldsm_x4(a0, a1, a2, a3, p_u32 + 4u * (aoff + kk));
            #pragma unroll
            for (int nt2 = 0; nt2 < 4; nt2++) {
                uint32_t b0, b1, b2, b3;
                ldsm_x4(b0, b1, b2, b3,
                        v_u32 + 4u * (boff + nt2 * 16 * FW + kk));
                mma_tf32(o[2 * nt2    ], a0, a1, a2, a3, b0, b2);
                mma_tf32(o[2 * nt2 + 1], a0, a1, a2, a3, b1, b3);
            }
        }
        __syncthreads();   // Ks/VsT consumed before next tile's stores
    }

    // normalize + write 'b n (h d)'
    float inv0 = 1.f / l0, inv1 = 1.f / l1;
    #pragma unroll
    for (int nt = 0; nt < 8; nt++) {
        int r = q0 + m0 + g;
        int c = hc + nt * 8 + 2 * qd;
        *(float2*)(out + (size_t)((size_t)b * SEQ + r) * DMODEL + c) =
            make_float2(o[nt][0] * inv0, o[nt][1] * inv0);
        *(float2*)(out + (size_t)((size_t)b * SEQ + r + 8) * DMODEL + c) =
            make_float2(o[nt][2] * inv1, o[nt][3] * inv1);
    }
}

// ---------------------------------------------------------------------------
extern "C" void kernel_launch(void* const* d_in, const int* in_sizes, int n_in,
                              void* d_out, int out_size) {
    const float* x     = (const float*)d_in[0];
    const float* W_qkv = (const float*)d_in[1];
    const float* W_out = (const float*)d_in[2];
    const float* b_out = (const float*)d_in[3];
    float* out = (float*)d_out;

    float* qkv;  cudaGetSymbolAddress((void**)&qkv,  g_qkv);
    float* attn; cudaGetSymbolAddress((void**)&attn, g_attn);

    cudaFuncSetAttribute(flash_tf32,
                         cudaFuncAttributeMaxDynamicSharedMemorySize,
                         FLASH_SMEM_BYTES);

    const int M = BATCH * SEQ;  // 8192

    gemm_tf32<<<dim3(QKVW / BN, M / BM), 256>>>(
        x, W_qkv, nullptr, qkv, M, QKVW, DMODEL);

    flash_tf32<<<dim3(SEQ / QT, HEADS, BATCH), 256, FLASH_SMEM_BYTES>>>(
        qkv, attn);

    gemm_tf32<<<dim3(DMODEL / BN, M / BM), 256>>>(
        attn, W_out, b_out, out, M, DMODEL, DMODEL);
}

// round 6
// speedup vs baseline: 1.2049x; 1.0958x over previous
#include <cuda_runtime.h>
#include <math.h>
#include <stdint.h>

#define HEADS   12
#define DH      64
#define SEQ     2048
#define BATCH   4
#define DMODEL  768
#define QKVW    2304      // 3 * 768
#define SCALE   0.125f    // 64^-0.5

// Scratch (device globals; no allocations allowed)
__device__ float g_qkv[(size_t)BATCH * SEQ * QKVW];    // tf32-rounded bits
__device__ float g_attn[(size_t)BATCH * SEQ * DMODEL];

// ---------------------------------------------------------------------------
// tf32 / ldmatrix helpers
// ---------------------------------------------------------------------------
__device__ __forceinline__ uint32_t f2tf32(float f) {
    uint32_t u;
    asm("cvt.rna.tf32.f32 %0, %1;" : "=r"(u) : "f"(f));
    return u;
}

__device__ __forceinline__ void mma_tf32(float c[4],
                                         uint32_t a0, uint32_t a1,
                                         uint32_t a2, uint32_t a3,
                                         uint32_t b0, uint32_t b1) {
    asm volatile(
        "mma.sync.aligned.m16n8k8.row.col.f32.tf32.tf32.f32 "
        "{%0,%1,%2,%3}, {%4,%5,%6,%7}, {%8,%9}, {%0,%1,%2,%3};\n"
        : "+f"(c[0]), "+f"(c[1]), "+f"(c[2]), "+f"(c[3])
        : "r"(a0), "r"(a1), "r"(a2), "r"(a3), "r"(b0), "r"(b1));
}

__device__ __forceinline__ void ldsm_x4(uint32_t& r0, uint32_t& r1,
                                        uint32_t& r2, uint32_t& r3,
                                        uint32_t addr) {
    asm volatile(
        "ldmatrix.sync.aligned.m8n8.x4.shared.b16 {%0,%1,%2,%3}, [%4];"
        : "=r"(r0), "=r"(r1), "=r"(r2), "=r"(r3) : "r"(addr));
}

// ---------------------------------------------------------------------------
// GEMM (tf32): C[M,N] = A[M,K] @ B[K,N] (+ bias), row-major.
// 128x128 tile, BK=32, 256 threads = 8 warps, warp tile 64x32.
// BS_W=136 -> B-fragment scalar LDS conflict-free (bank = 8q+g).
// round_out: store tf32-rounded bits (for the qkv intermediate).
// ---------------------------------------------------------------------------
#define BM 128
#define BN 128
#define BK 32
#define AS_W (BK + 4)     // 36
#define BS_W (BN + 8)     // 136

__global__ __launch_bounds__(256)
void gemm_tf32(const float* __restrict__ A, const float* __restrict__ B,
               const float* __restrict__ bias, float* __restrict__ C,
               int M, int N, int K, int round_out) {
    __shared__ uint32_t As[BM * AS_W];
    __shared__ uint32_t Bs[BK * BS_W];

    int tid  = threadIdx.x;
    int lane = tid & 31, wid = tid >> 5;
    int wm = (wid >> 2) * 64;
    int wn = (wid & 3) * 32;
    int g  = lane >> 2, q = lane & 3;
    uint32_t lr = lane & 15, ls = (lane >> 4) * 4;

    uint32_t as_u32 = (uint32_t)__cvta_generic_to_shared(As);
    uint32_t a_off  = (wm + lr) * AS_W + ls;

    int row0 = blockIdx.y * BM, col0 = blockIdx.x * BN;

    int aRow = tid >> 3, aCol = (tid & 7) << 2;
    int bRow = tid >> 5, bCol = (tid & 31) << 2;

    float acc[4][4][4] = {};
    float4 pa[4], pb[4];

    #pragma unroll
    for (int i = 0; i < 4; i++)
        pa[i] = *(const float4*)(A + (size_t)(row0 + aRow + 32 * i) * K + aCol);
    #pragma unroll
    for (int i = 0; i < 4; i++)
        pb[i] = *(const float4*)(B + (size_t)(bRow + 8 * i) * N + col0 + bCol);

    for (int k0 = 0; k0 < K; k0 += BK) {
        #pragma unroll
        for (int i = 0; i < 4; i++)
            *(uint4*)&As[(aRow + 32 * i) * AS_W + aCol] =
                make_uint4(f2tf32(pa[i].x), f2tf32(pa[i].y), f2tf32(pa[i].z), f2tf32(pa[i].w));
        #pragma unroll
        for (int i = 0; i < 4; i++)
            *(uint4*)&Bs[(bRow + 8 * i) * BS_W + bCol] =
                make_uint4(f2tf32(pb[i].x), f2tf32(pb[i].y), f2tf32(pb[i].z), f2tf32(pb[i].w));
        __syncthreads();

        int kn = k0 + BK;
        if (kn < K) {
            #pragma unroll
            for (int i = 0; i < 4; i++)
                pa[i] = *(const float4*)(A + (size_t)(row0 + aRow + 32 * i) * K + kn + aCol);
            #pragma unroll
            for (int i = 0; i < 4; i++)
                pb[i] = *(const float4*)(B + (size_t)(kn + bRow + 8 * i) * N + col0 + bCol);
        }

        #pragma unroll
        for (int ks = 0; ks < BK / 8; ks++) {
            int kk = ks * 8;
            uint32_t af[4][4];
            #pragma unroll
            for (int mt = 0; mt < 4; mt++)
                ldsm_x4(af[mt][0], af[mt][1], af[mt][2], af[mt][3],
                        as_u32 + 4u * (a_off + mt * 16 * AS_W + kk));
            uint32_t bf[4][2];
            #pragma unroll
            for (int nt = 0; nt < 4; nt++) {
                int c = wn + nt * 8 + g;
                bf[nt][0] = Bs[(kk + q    ) * BS_W + c];
                bf[nt][1] = Bs[(kk + q + 4) * BS_W + c];
            }
            #pragma unroll
            for (int mt = 0; mt < 4; mt++)
                #pragma unroll
                for (int nt = 0; nt < 4; nt++)
                    mma_tf32(acc[mt][nt], af[mt][0], af[mt][1], af[mt][2], af[mt][3],
                             bf[nt][0], bf[nt][1]);
        }
        __syncthreads();
    }

    #pragma unroll
    for (int mt = 0; mt < 4; mt++) {
        int r = row0 + wm + mt * 16 + g;
        #pragma unroll
        for (int nt = 0; nt < 4; nt++) {
            int c = col0 + wn + nt * 8 + 2 * q;
            float bx = 0.f, by = 0.f;
            if (bias) { bx = bias[c]; by = bias[c + 1]; }
            float v0 = acc[mt][nt][0] + bx, v1 = acc[mt][nt][1] + by;
            float v2 = acc[mt][nt][2] + bx, v3 = acc[mt][nt][3] + by;
            if (round_out) {
                v0 = __uint_as_float(f2tf32(v0));
                v1 = __uint_as_float(f2tf32(v1));
                v2 = __uint_as_float(f2tf32(v2));
                v3 = __uint_as_float(f2tf32(v3));
            }
            *(float2*)(C + (size_t)r * N + c) = make_float2(v0, v1);
            *(float2*)(C + (size_t)(r + 8) * N + c) = make_float2(v2, v3);
        }
    }
}

// ---------------------------------------------------------------------------
// Flash attention (tf32): block = (b, h, 64-row Q tile), 4 warps, KT=32.
// ~44.5 KB smem -> 4-5 CTAs/SM: cross-CTA warps hide the softmax chain,
// LDG latency and barriers. qkv is tf32-pre-rounded (no cvt here).
// Q[64][68], K[32][68]: A/B frags via ldmatrix. V[32][72] natural: PV
// B-frags via conflict-free scalar LDS (72 mod 32 = 8 -> bank 8q+g).
// P[64][36] staged per-warp. Online softmax in C-fragment registers.
// ---------------------------------------------------------------------------
#define QT  64
#define KT  32
#define QW  68
#define KW  68
#define VW  72
#define PW  36
#define FLASH_SMEM_BYTES ((QT * QW + KT * KW + KT * VW + QT * PW) * 4)

__global__ __launch_bounds__(128)
void flash_tf32(const float* __restrict__ qkv, float* __restrict__ out) {
    extern __shared__ float sm[];
    float* Qs = sm;                                   // [QT][QW] Q*SCALE
    float* Ks = sm + QT * QW;                         // [KT][KW]
    float* Vs = sm + QT * QW + KT * KW;               // [KT][VW] natural
    float* Ps = sm + QT * QW + KT * KW + KT * VW;     // [QT][PW]

    int b  = blockIdx.z, h = blockIdx.y;
    int q0 = blockIdx.x * QT;
    int tid = threadIdx.x;
    int lane = tid & 31, wid = tid >> 5;
    int g = lane >> 2, qd = lane & 3;
    int m0 = wid * 16;
    uint32_t lr = lane & 15, ls = (lane >> 4) * 4;

    uint32_t q_u32 = (uint32_t)__cvta_generic_to_shared(Qs);
    uint32_t k_u32 = (uint32_t)__cvta_generic_to_shared(Ks);
    uint32_t p_u32 = (uint32_t)__cvta_generic_to_shared(Ps);

    uint32_t aoffQ = (m0 + lr) * QW + ls;
    uint32_t aoffP = (m0 + lr) * PW + ls;
    uint32_t boffK = lr * KW + ls;

    const float* base = qkv + (size_t)b * SEQ * QKVW;
    int hc = h * DH;

    // Q tile [64][64]: bits already tf32; *SCALE (2^-3) is exact
    #pragma unroll
    for (int i = 0; i < 8; i++) {
        int f = tid + i * 128;
        int r = f >> 4, c = (f & 15) << 2;
        float4 v = *(const float4*)(base + (size_t)(q0 + r) * QKVW + hc + c);
        *(float4*)&Qs[r * QW + c] =
            make_float4(v.x * SCALE, v.y * SCALE, v.z * SCALE, v.w * SCALE);
    }

    float o[8][4] = {};
    float mr0 = -INFINITY, mr1 = -INFINITY, l0 = 0.f, l1 = 0.f;
    __syncthreads();

    for (int kt = 0; kt < SEQ / KT; kt++) {
        int k0 = kt * KT;
        #pragma unroll
        for (int i = 0; i < 4; i++) {
            int f = tid + i * 128;
            int r = f >> 4, c = (f & 15) << 2;
            const float* src = base + (size_t)(k0 + r) * QKVW + hc + c;
            *(float4*)&Ks[r * KW + c] = *(const float4*)(src + DMODEL);
            *(float4*)&Vs[r * VW + c] = *(const float4*)(src + 2 * DMODEL);
        }
        __syncthreads();

        // S(16x32) = Qstrip @ K^T
        float s[4][4] = {};
        #pragma unroll
        for (int ks = 0; ks < 8; ks++) {
            int kk = ks * 8;
            uint32_t a0, a1, a2, a3;
            ldsm_x4(a0, a1, a2, a3, q_u32 + 4u * (aoffQ + kk));
            #pragma unroll
            for (int nt2 = 0; nt2 < 2; nt2++) {
                uint32_t b0, b1, b2, b3;
                ldsm_x4(b0, b1, b2, b3,
                        k_u32 + 4u * (boffK + nt2 * 16 * KW + kk));
                mma_tf32(s[2 * nt2    ], a0, a1, a2, a3, b0, b2);
                mma_tf32(s[2 * nt2 + 1], a0, a1, a2, a3, b1, b3);
            }
        }

        // online softmax: rows (m0+g), (m0+g+8); quad-lane reduce
        float mx0 = -INFINITY, mx1 = -INFINITY;
        #pragma unroll
        for (int nt = 0; nt < 4; nt++) {
            mx0 = fmaxf(mx0, fmaxf(s[nt][0], s[nt][1]));
            mx1 = fmaxf(mx1, fmaxf(s[nt][2], s[nt][3]));
        }
        #pragma unroll
        for (int w = 1; w < 4; w <<= 1) {
            mx0 = fmaxf(mx0, __shfl_xor_sync(0xffffffffu, mx0, w));
            mx1 = fmaxf(mx1, __shfl_xor_sync(0xffffffffu, mx1, w));
        }
        float mn0 = fmaxf(mr0, mx0), mn1 = fmaxf(mr1, mx1);
        float al0 = __expf(mr0 - mn0), al1 = __expf(mr1 - mn1);
        mr0 = mn0; mr1 = mn1;

        float sum0 = 0.f, sum1 = 0.f;
        #pragma unroll
        for (int nt = 0; nt < 4; nt++) {
            s[nt][0] = __expf(s[nt][0] - mn0); sum0 += s[nt][0];
            s[nt][1] = __expf(s[nt][1] - mn0); sum0 += s[nt][1];
            s[nt][2] = __expf(s[nt][2] - mn1); sum1 += s[nt][2];
            s[nt][3] = __expf(s[nt][3] - mn1); sum1 += s[nt][3];
        }
        #pragma unroll
        for (int w = 1; w < 4; w <<= 1) {
            sum0 += __shfl_xor_sync(0xffffffffu, sum0, w);
            sum1 += __shfl_xor_sync(0xffffffffu, sum1, w);
        }
        l0 = l0 * al0 + sum0;
        l1 = l1 * al1 + sum1;

        // stage P (tf32) into warp-private rows
        #pragma unroll
        for (int nt = 0; nt < 4; nt++) {
            int c = nt * 8 + 2 * qd;
            Ps[(m0 + g    ) * PW + c    ] = __uint_as_float(f2tf32(s[nt][0]));
            Ps[(m0 + g    ) * PW + c + 1] = __uint_as_float(f2tf32(s[nt][1]));
            Ps[(m0 + g + 8) * PW + c    ] = __uint_as_float(f2tf32(s[nt][2]));
            Ps[(m0 + g + 8) * PW + c + 1] = __uint_as_float(f2tf32(s[nt][3]));
        }
        __syncwarp();

        // O = O*alpha + P @ V  (B-frags: scalar LDS from natural V)
        #pragma unroll
        for (int nt = 0; nt < 8; nt++) {
            o[nt][0] *= al0; o[nt][1] *= al0;
            o[nt][2] *= al1; o[nt][3] *= al1;
        }
        #pragma unroll
        for (int ks = 0; ks < 4; ks++) {
            int kk = ks * 8;
            uint32_t a0, a1, a2, a3;
            ldsm_x4(a0, a1, a2, a3, p_u32 + 4u * (aoffP + kk));
            #pragma unroll
            for (int nt = 0; nt < 8; nt++) {
                uint32_t b0 = __float_as_uint(Vs[(kk + qd    ) * VW + nt * 8 + g]);
                uint32_t b1 = __float_as_uint(Vs[(kk + qd + 4) * VW + nt * 8 + g]);
                mma_tf32(o[nt], a0, a1, a2, a3, b0, b1);
            }
        }
        __syncthreads();   // Ks/Vs consumed before next tile's stores
    }

    // normalize + write 'b n (h d)'
    float inv0 = 1.f / l0, inv1 = 1.f / l1;
    #pragma unroll
    for (int nt = 0; nt < 8; nt++) {
        int r = q0 + m0 + g;
        int c = hc + nt * 8 + 2 * qd;
        *(float2*)(out + (size_t)((size_t)b * SEQ + r) * DMODEL + c) =
            make_float2(o[nt][0] * inv0, o[nt][1] * inv0);
        *(float2*)(out + (size_t)((size_t)b * SEQ + r + 8) * DMODEL + c) =
            make_float2(o[nt][2] * inv1, o[nt][3] * inv1);
    }
}

// ---------------------------------------------------------------------------
extern "C" void kernel_launch(void* const* d_in, const int* in_sizes, int n_in,
                              void* d_out, int out_size) {
    const float* x     = (const float*)d_in[0];
    const float* W_qkv = (const float*)d_in[1];
    const float* W_out = (const float*)d_in[2];
    const float* b_out = (const float*)d_in[3];
    float* out = (float*)d_out;

    float* qkv;  cudaGetSymbolAddress((void**)&qkv,  g_qkv);
    float* attn; cudaGetSymbolAddress((void**)&attn, g_attn);

    cudaFuncSetAttribute(flash_tf32,
                         cudaFuncAttributeMaxDynamicSharedMemorySize,
                         FLASH_SMEM_BYTES);

    const int M = BATCH * SEQ;  // 8192

    // 1) qkv = x @ W_qkv  (tf32-pre-rounded output)
    gemm_tf32<<<dim3(QKVW / BN, M / BM), 256>>>(
        x, W_qkv, nullptr, qkv, M, QKVW, DMODEL, 1);

    // 2) attention per (b, h, q-tile)
    flash_tf32<<<dim3(SEQ / QT, HEADS, BATCH), 128, FLASH_SMEM_BYTES>>>(
        qkv, attn);

    // 3) out = attn @ W_out + b_out
    gemm_tf32<<<dim3(DMODEL / BN, M / BM), 256>>>(
        attn, W_out, b_out, out, M, DMODEL, DMODEL, 0);
}

// round 7
// speedup vs baseline: 1.2234x; 1.0154x over previous
#include <cuda_runtime.h>
#include <math.h>
#include <stdint.h>

#define HEADS   12
#define DH      64
#define SEQ     2048
#define BATCH   4
#define DMODEL  768
#define QKVW    2304      // 3 * 768
#define SCALE   0.125f    // 64^-0.5

// Scratch (device globals; no allocations allowed)
__device__ float g_qkv[(size_t)BATCH * SEQ * QKVW];    // tf32-rounded bits
__device__ float g_attn[(size_t)BATCH * SEQ * DMODEL];

// ---------------------------------------------------------------------------
// tf32 / ldmatrix / cp.async helpers
// ---------------------------------------------------------------------------
__device__ __forceinline__ uint32_t f2tf32(float f) {
    uint32_t u;
    asm("cvt.rna.tf32.f32 %0, %1;" : "=r"(u) : "f"(f));
    return u;
}

__device__ __forceinline__ void mma_tf32(float c[4],
                                         uint32_t a0, uint32_t a1,
                                         uint32_t a2, uint32_t a3,
                                         uint32_t b0, uint32_t b1) {
    asm volatile(
        "mma.sync.aligned.m16n8k8.row.col.f32.tf32.tf32.f32 "
        "{%0,%1,%2,%3}, {%4,%5,%6,%7}, {%8,%9}, {%0,%1,%2,%3};\n"
        : "+f"(c[0]), "+f"(c[1]), "+f"(c[2]), "+f"(c[3])
        : "r"(a0), "r"(a1), "r"(a2), "r"(a3), "r"(b0), "r"(b1));
}

__device__ __forceinline__ void ldsm_x4(uint32_t& r0, uint32_t& r1,
                                        uint32_t& r2, uint32_t& r3,
                                        uint32_t addr) {
    asm volatile(
        "ldmatrix.sync.aligned.m8n8.x4.shared.b16 {%0,%1,%2,%3}, [%4];"
        : "=r"(r0), "=r"(r1), "=r"(r2), "=r"(r3) : "r"(addr));
}

__device__ __forceinline__ void cp_async16(uint32_t dst_smem, const void* src) {
    asm volatile("cp.async.cg.shared.global [%0], [%1], 16;"
                 :: "r"(dst_smem), "l"(src));
}
__device__ __forceinline__ void cp_commit() {
    asm volatile("cp.async.commit_group;");
}
__device__ __forceinline__ void cp_wait_all() {
    asm volatile("cp.async.wait_group 0;");
}

// ---------------------------------------------------------------------------
// GEMM (tf32): unchanged from round 6 (214us, tensor 51%).
// ---------------------------------------------------------------------------
#define BM 128
#define BN 128
#define BK 32
#define AS_W (BK + 4)     // 36
#define BS_W (BN + 8)     // 136

__global__ __launch_bounds__(256)
void gemm_tf32(const float* __restrict__ A, const float* __restrict__ B,
               const float* __restrict__ bias, float* __restrict__ C,
               int M, int N, int K, int round_out) {
    __shared__ uint32_t As[BM * AS_W];
    __shared__ uint32_t Bs[BK * BS_W];

    int tid  = threadIdx.x;
    int lane = tid & 31, wid = tid >> 5;
    int wm = (wid >> 2) * 64;
    int wn = (wid & 3) * 32;
    int g  = lane >> 2, q = lane & 3;
    uint32_t lr = lane & 15, ls = (lane >> 4) * 4;

    uint32_t as_u32 = (uint32_t)__cvta_generic_to_shared(As);
    uint32_t a_off  = (wm + lr) * AS_W + ls;

    int row0 = blockIdx.y * BM, col0 = blockIdx.x * BN;

    int aRow = tid >> 3, aCol = (tid & 7) << 2;
    int bRow = tid >> 5, bCol = (tid & 31) << 2;

    float acc[4][4][4] = {};
    float4 pa[4], pb[4];

    #pragma unroll
    for (int i = 0; i < 4; i++)
        pa[i] = *(const float4*)(A + (size_t)(row0 + aRow + 32 * i) * K + aCol);
    #pragma unroll
    for (int i = 0; i < 4; i++)
        pb[i] = *(const float4*)(B + (size_t)(bRow + 8 * i) * N + col0 + bCol);

    for (int k0 = 0; k0 < K; k0 += BK) {
        #pragma unroll
        for (int i = 0; i < 4; i++)
            *(uint4*)&As[(aRow + 32 * i) * AS_W + aCol] =
                make_uint4(f2tf32(pa[i].x), f2tf32(pa[i].y), f2tf32(pa[i].z), f2tf32(pa[i].w));
        #pragma unroll
        for (int i = 0; i < 4; i++)
            *(uint4*)&Bs[(bRow + 8 * i) * BS_W + bCol] =
                make_uint4(f2tf32(pb[i].x), f2tf32(pb[i].y), f2tf32(pb[i].z), f2tf32(pb[i].w));
        __syncthreads();

        int kn = k0 + BK;
        if (kn < K) {
            #pragma unroll
            for (int i = 0; i < 4; i++)
                pa[i] = *(const float4*)(A + (size_t)(row0 + aRow + 32 * i) * K + kn + aCol);
            #pragma unroll
            for (int i = 0; i < 4; i++)
                pb[i] = *(const float4*)(B + (size_t)(kn + bRow + 8 * i) * N + col0 + bCol);
        }

        #pragma unroll
        for (int ks = 0; ks < BK / 8; ks++) {
            int kk = ks * 8;
            uint32_t af[4][4];
            #pragma unroll
            for (int mt = 0; mt < 4; mt++)
                ldsm_x4(af[mt][0], af[mt][1], af[mt][2], af[mt][3],
                        as_u32 + 4u * (a_off + mt * 16 * AS_W + kk));
            uint32_t bf[4][2];
            #pragma unroll
            for (int nt = 0; nt < 4; nt++) {
                int c = wn + nt * 8 + g;
                bf[nt][0] = Bs[(kk + q    ) * BS_W + c];
                bf[nt][1] = Bs[(kk + q + 4) * BS_W + c];
            }
            #pragma unroll
            for (int mt = 0; mt < 4; mt++)
                #pragma unroll
                for (int nt = 0; nt < 4; nt++)
                    mma_tf32(acc[mt][nt], af[mt][0], af[mt][1], af[mt][2], af[mt][3],
                             bf[nt][0], bf[nt][1]);
        }
        __syncthreads();
    }

    #pragma unroll
    for (int mt = 0; mt < 4; mt++) {
        int r = row0 + wm + mt * 16 + g;
        #pragma unroll
        for (int nt = 0; nt < 4; nt++) {
            int c = col0 + wn + nt * 8 + 2 * q;
            float bx = 0.f, by = 0.f;
            if (bias) { bx = bias[c]; by = bias[c + 1]; }
            float v0 = acc[mt][nt][0] + bx, v1 = acc[mt][nt][1] + by;
            float v2 = acc[mt][nt][2] + bx, v3 = acc[mt][nt][3] + by;
            if (round_out) {
                v0 = __uint_as_float(f2tf32(v0));
                v1 = __uint_as_float(f2tf32(v1));
                v2 = __uint_as_float(f2tf32(v2));
                v3 = __uint_as_float(f2tf32(v3));
            }
            *(float2*)(C + (size_t)r * N + c) = make_float2(v0, v1);
            *(float2*)(C + (size_t)(r + 8) * N + c) = make_float2(v2, v3);
        }
    }
}

// ---------------------------------------------------------------------------
// Flash attention (tf32): block = (b, h, 64-row Q tile), 4 warps, KT=64.
// K/V double-buffered via cp.async: tile t+1's loads issued right after
// tile t's barrier, awaited at top of t+1 -> latency hidden by compute.
// One __syncthreads per tile. qkv bits are tf32-pre-rounded (no cvt here).
// Q/K/P stride 68 (ldmatrix conflict-free); V natural [kv][d] stride 72
// (scalar B-frag LDS bank = 8*qd+g, conflict-free).
// smem 106.5 KB -> 2 CTAs/SM.
// ---------------------------------------------------------------------------
#define QT  64
#define KT  64
#define QW  68
#define KW  68
#define VW  72
#define PW  68
#define FLASH_SMEM_FLOATS (QT*QW + 2*KT*KW + 2*KT*VW + QT*PW)
#define FLASH_SMEM_BYTES  (FLASH_SMEM_FLOATS * 4)

__global__ __launch_bounds__(128)
void flash_tf32(const float* __restrict__ qkv, float* __restrict__ out) {
    extern __shared__ float sm[];
    float* Qs    = sm;                               // [QT][QW]  Q*SCALE
    float* Ks[2] = { sm + QT * QW,
                     sm + QT * QW + KT * KW };       // [KT][KW]
    float* Vs[2] = { sm + QT * QW + 2 * KT * KW,
                     sm + QT * QW + 2 * KT * KW + KT * VW };  // [KT][VW]
    float* Ps    = sm + QT * QW + 2 * KT * (KW + VW);         // [QT][PW]

    int b  = blockIdx.z, h = blockIdx.y;
    int q0 = blockIdx.x * QT;
    int tid = threadIdx.x;
    int lane = tid & 31, wid = tid >> 5;
    int g = lane >> 2, qd = lane & 3;
    int m0 = wid * 16;
    uint32_t lr = lane & 15, ls = (lane >> 4) * 4;

    uint32_t q_u32 = (uint32_t)__cvta_generic_to_shared(Qs);
    uint32_t k_u32[2] = { (uint32_t)__cvta_generic_to_shared(Ks[0]),
                          (uint32_t)__cvta_generic_to_shared(Ks[1]) };
    uint32_t v_u32[2] = { (uint32_t)__cvta_generic_to_shared(Vs[0]),
                          (uint32_t)__cvta_generic_to_shared(Vs[1]) };
    uint32_t p_u32 = (uint32_t)__cvta_generic_to_shared(Ps);

    uint32_t aoffQ = (m0 + lr) * QW + ls;
    uint32_t aoffP = (m0 + lr) * PW + ls;
    uint32_t boffK = lr * KW + ls;

    const float* base = qkv + (size_t)b * SEQ * QKVW;
    int hc = h * DH;

    // per-thread copy slots: 8 rows apart, row = (tid>>4) + 8i, col = (tid&15)*4
    int cr = tid >> 4, cc = (tid & 15) << 2;

    // prefetch tile 0 K/V
    #pragma unroll
    for (int i = 0; i < 8; i++) {
        int r = cr + 8 * i;
        const float* src = base + (size_t)r * QKVW + hc + cc;
        cp_async16(k_u32[0] + 4u * (r * KW + cc), src + DMODEL);
        cp_async16(v_u32[0] + 4u * (r * VW + cc), src + 2 * DMODEL);
    }
    cp_commit();

    // Q tile [64][64]: bits already tf32; *SCALE (2^-3) exact
    #pragma unroll
    for (int i = 0; i < 8; i++) {
        int r = cr + 8 * i;
        float4 v = *(const float4*)(base + (size_t)(q0 + r) * QKVW + hc + cc);
        *(float4*)&Qs[r * QW + cc] =
            make_float4(v.x * SCALE, v.y * SCALE, v.z * SCALE, v.w * SCALE);
    }

    float o[8][4] = {};
    float mr0 = -INFINITY, mr1 = -INFINITY, l0 = 0.f, l1 = 0.f;

    const int NT = SEQ / KT;   // 32
    for (int kt = 0; kt < NT; kt++) {
        int buf = kt & 1;
        cp_wait_all();
        __syncthreads();

        if (kt + 1 < NT) {
            int nbuf = buf ^ 1;
            int k0n = (kt + 1) * KT;
            #pragma unroll
            for (int i = 0; i < 8; i++) {
                int r = cr + 8 * i;
                const float* src = base + (size_t)(k0n + r) * QKVW + hc + cc;
                cp_async16(k_u32[nbuf] + 4u * (r * KW + cc), src + DMODEL);
                cp_async16(v_u32[nbuf] + 4u * (r * VW + cc), src + 2 * DMODEL);
            }
            cp_commit();
        }

        // S(16x64) = Qstrip @ K^T
        float s[8][4] = {};
        #pragma unroll
        for (int ks = 0; ks < 8; ks++) {
            int kk = ks * 8;
            uint32_t a0, a1, a2, a3;
            ldsm_x4(a0, a1, a2, a3, q_u32 + 4u * (aoffQ + kk));
            #pragma unroll
            for (int nt2 = 0; nt2 < 4; nt2++) {
                uint32_t b0, b1, b2, b3;
                ldsm_x4(b0, b1, b2, b3,
                        k_u32[buf] + 4u * (boffK + nt2 * 16 * KW + kk));
                mma_tf32(s[2 * nt2    ], a0, a1, a2, a3, b0, b2);
                mma_tf32(s[2 * nt2 + 1], a0, a1, a2, a3, b1, b3);
            }
        }

        // online softmax: rows (m0+g), (m0+g+8); quad-lane reduce
        float mx0 = -INFINITY, mx1 = -INFINITY;
        #pragma unroll
        for (int nt = 0; nt < 8; nt++) {
            mx0 = fmaxf(mx0, fmaxf(s[nt][0], s[nt][1]));
            mx1 = fmaxf(mx1, fmaxf(s[nt][2], s[nt][3]));
        }
        #pragma unroll
        for (int w = 1; w < 4; w <<= 1) {
            mx0 = fmaxf(mx0, __shfl_xor_sync(0xffffffffu, mx0, w));
            mx1 = fmaxf(mx1, __shfl_xor_sync(0xffffffffu, mx1, w));
        }
        float mn0 = fmaxf(mr0, mx0), mn1 = fmaxf(mr1, mx1);
        float al0 = __expf(mr0 - mn0), al1 = __expf(mr1 - mn1);
        mr0 = mn0; mr1 = mn1;

        float sum0 = 0.f, sum1 = 0.f;
        #pragma unroll
        for (int nt = 0; nt < 8; nt++) {
            s[nt][0] = __expf(s[nt][0] - mn0); sum0 += s[nt][0];
            s[nt][1] = __expf(s[nt][1] - mn0); sum0 += s[nt][1];
            s[nt][2] = __expf(s[nt][2] - mn1); sum1 += s[nt][2];
            s[nt][3] = __expf(s[nt][3] - mn1); sum1 += s[nt][3];
        }
        #pragma unroll
        for (int w = 1; w < 4; w <<= 1) {
            sum0 += __shfl_xor_sync(0xffffffffu, sum0, w);
            sum1 += __shfl_xor_sync(0xffffffffu, sum1, w);
        }
        l0 = l0 * al0 + sum0;
        l1 = l1 * al1 + sum1;

        // stage P (tf32) into warp-private rows
        #pragma unroll
        for (int nt = 0; nt < 8; nt++) {
            int c = nt * 8 + 2 * qd;
            Ps[(m0 + g    ) * PW + c    ] = __uint_as_float(f2tf32(s[nt][0]));
            Ps[(m0 + g    ) * PW + c + 1] = __uint_as_float(f2tf32(s[nt][1]));
            Ps[(m0 + g + 8) * PW + c    ] = __uint_as_float(f2tf32(s[nt][2]));
            Ps[(m0 + g + 8) * PW + c + 1] = __uint_as_float(f2tf32(s[nt][3]));
        }
        __syncwarp();

        // O = O*alpha + P @ V
        #pragma unroll
        for (int nt = 0; nt < 8; nt++) {
            o[nt][0] *= al0; o[nt][1] *= al0;
            o[nt][2] *= al1; o[nt][3] *= al1;
        }
        const float* Vb = Vs[buf];
        #pragma unroll
        for (int ks = 0; ks < 8; ks++) {
            int kk = ks * 8;
            uint32_t a0, a1, a2, a3;
            ldsm_x4(a0, a1, a2, a3, p_u32 + 4u * (aoffP + kk));
            #pragma unroll
            for (int nt = 0; nt < 8; nt++) {
                uint32_t b0 = __float_as_uint(Vb[(kk + qd    ) * VW + nt * 8 + g]);
                uint32_t b1 = __float_as_uint(Vb[(kk + qd + 4) * VW + nt * 8 + g]);
                mma_tf32(o[nt], a0, a1, a2, a3, b0, b1);
            }
        }
    }

    // normalize + write 'b n (h d)'
    float inv0 = 1.f / l0, inv1 = 1.f / l1;
    #pragma unroll
    for (int nt = 0; nt < 8; nt++) {
        int r = q0 + m0 + g;
        int c = hc + nt * 8 + 2 * qd;
        *(float2*)(out + (size_t)((size_t)b * SEQ + r) * DMODEL + c) =
            make_float2(o[nt][0] * inv0, o[nt][1] * inv0);
        *(float2*)(out + (size_t)((size_t)b * SEQ + r + 8) * DMODEL + c) =
            make_float2(o[nt][2] * inv1, o[nt][3] * inv1);
    }
}

// ---------------------------------------------------------------------------
extern "C" void kernel_launch(void* const* d_in, const int* in_sizes, int n_in,
                              void* d_out, int out_size) {
    const float* x     = (const float*)d_in[0];
    const float* W_qkv = (const float*)d_in[1];
    const float* W_out = (const float*)d_in[2];
    const float* b_out = (const float*)d_in[3];
    float* out = (float*)d_out;

    float* qkv;  cudaGetSymbolAddress((void**)&qkv,  g_qkv);
    float* attn; cudaGetSymbolAddress((void**)&attn, g_attn);

    cudaFuncSetAttribute(flash_tf32,
                         cudaFuncAttributeMaxDynamicSharedMemorySize,
                         FLASH_SMEM_BYTES);

    const int M = BATCH * SEQ;  // 8192

    // 1) qkv = x @ W_qkv  (tf32-pre-rounded output)
    gemm_tf32<<<dim3(QKVW / BN, M / BM), 256>>>(
        x, W_qkv, nullptr, qkv, M, QKVW, DMODEL, 1);

    // 2) attention per (b, h, q-tile)
    flash_tf32<<<dim3(SEQ / QT, HEADS, BATCH), 128, FLASH_SMEM_BYTES>>>(
        qkv, attn);

    // 3) out = attn @ W_out + b_out
    gemm_tf32<<<dim3(DMODEL / BN, M / BM), 256>>>(
        attn, W_out, b_out, out, M, DMODEL, DMODEL, 0);
}

// round 8
// speedup vs baseline: 2.0060x; 1.6397x over previous
#include <cuda_runtime.h>
#include <cuda_fp16.h>
#include <math.h>
#include <stdint.h>

#define HEADS   12
#define DH      64
#define SEQ     2048
#define BATCH   4
#define DMODEL  768
#define QKVW    2304      // 3 * 768
#define SCALE   0.125f    // 64^-0.5

// Scratch (device globals; no allocations allowed)
__device__ __half g_qkv[(size_t)BATCH * SEQ * QKVW];   // fp16-rounded qkv
__device__ float  g_attn[(size_t)BATCH * SEQ * DMODEL];

// ---------------------------------------------------------------------------
// fp16 mma / ldmatrix / cp.async helpers
// ---------------------------------------------------------------------------
__device__ __forceinline__ void mma_f16(float c[4],
                                        uint32_t a0, uint32_t a1,
                                        uint32_t a2, uint32_t a3,
                                        uint32_t b0, uint32_t b1) {
    asm volatile(
        "mma.sync.aligned.m16n8k16.row.col.f32.f16.f16.f32 "
        "{%0,%1,%2,%3}, {%4,%5,%6,%7}, {%8,%9}, {%0,%1,%2,%3};\n"
        : "+f"(c[0]), "+f"(c[1]), "+f"(c[2]), "+f"(c[3])
        : "r"(a0), "r"(a1), "r"(a2), "r"(a3), "r"(b0), "r"(b1));
}

__device__ __forceinline__ void ldsm_x4(uint32_t& r0, uint32_t& r1,
                                        uint32_t& r2, uint32_t& r3,
                                        uint32_t addr) {
    asm volatile(
        "ldmatrix.sync.aligned.m8n8.x4.shared.b16 {%0,%1,%2,%3}, [%4];"
        : "=r"(r0), "=r"(r1), "=r"(r2), "=r"(r3) : "r"(addr));
}

__device__ __forceinline__ void ldsm_x4_t(uint32_t& r0, uint32_t& r1,
                                          uint32_t& r2, uint32_t& r3,
                                          uint32_t addr) {
    asm volatile(
        "ldmatrix.sync.aligned.m8n8.x4.trans.shared.b16 {%0,%1,%2,%3}, [%4];"
        : "=r"(r0), "=r"(r1), "=r"(r2), "=r"(r3) : "r"(addr));
}

__device__ __forceinline__ void cp_async16(uint32_t dst_smem, const void* src) {
    asm volatile("cp.async.cg.shared.global [%0], [%1], 16;"
                 :: "r"(dst_smem), "l"(src));
}
__device__ __forceinline__ void cp_commit() {
    asm volatile("cp.async.commit_group;");
}
__device__ __forceinline__ void cp_wait_all() {
    asm volatile("cp.async.wait_group 0;");
}

// ---------------------------------------------------------------------------
// GEMM (fp16 mma, fp32 accum): C[M,N] = A[M,K] @ B[K,N] (+ bias), row-major.
// 128x128 tile, BK=32, 256 threads = 8 warps, warp tile 64x32.
// A smem [128][40]h (stride 80B), B smem [32][136]h (stride 272B):
// both ldmatrix conflict-free (r*stride mod 128 distinct per 8 rows).
// B fragments via ldmatrix.trans. out_half: emit __half (for qkv).
// ---------------------------------------------------------------------------
#define BM 128
#define BN 128
#define BK 32
#define AW 40     // halves
#define BW 136    // halves

__global__ __launch_bounds__(256)
void gemm_f16(const float* __restrict__ A, const float* __restrict__ B,
              const float* __restrict__ bias, void* __restrict__ Cout,
              int M, int N, int K, int out_half) {
    __shared__ __half As[BM * AW];
    __shared__ __half Bs[BK * BW];

    int tid  = threadIdx.x;
    int lane = tid & 31, wid = tid >> 5;
    int wm = (wid >> 2) * 64;
    int wn = (wid & 3) * 32;
    int g  = lane >> 2, q = lane & 3;
    uint32_t lr = lane & 15, lhi = (lane >> 4) * 8;   // halves

    uint32_t as_u32 = (uint32_t)__cvta_generic_to_shared(As);
    uint32_t bs_u32 = (uint32_t)__cvta_generic_to_shared(Bs);

    int row0 = blockIdx.y * BM, col0 = blockIdx.x * BN;

    int aRow = tid >> 3, aCol = (tid & 7) << 2;   // A: 128x32 f32, 4 f4/thr
    int bRow = tid >> 5, bCol = (tid & 31) << 2;  // B: 32x128 f32, 4 f4/thr

    float acc[4][4][4] = {};
    float4 pa[4], pb[4];

    #pragma unroll
    for (int i = 0; i < 4; i++)
        pa[i] = *(const float4*)(A + (size_t)(row0 + aRow + 32 * i) * K + aCol);
    #pragma unroll
    for (int i = 0; i < 4; i++)
        pb[i] = *(const float4*)(B + (size_t)(bRow + 8 * i) * N + col0 + bCol);

    for (int k0 = 0; k0 < K; k0 += BK) {
        #pragma unroll
        for (int i = 0; i < 4; i++) {
            __half* d = &As[(aRow + 32 * i) * AW + aCol];
            *(__half2*)(d)     = __floats2half2_rn(pa[i].x, pa[i].y);
            *(__half2*)(d + 2) = __floats2half2_rn(pa[i].z, pa[i].w);
        }
        #pragma unroll
        for (int i = 0; i < 4; i++) {
            __half* d = &Bs[(bRow + 8 * i) * BW + bCol];
            *(__half2*)(d)     = __floats2half2_rn(pb[i].x, pb[i].y);
            *(__half2*)(d + 2) = __floats2half2_rn(pb[i].z, pb[i].w);
        }
        __syncthreads();

        int kn = k0 + BK;
        if (kn < K) {
            #pragma unroll
            for (int i = 0; i < 4; i++)
                pa[i] = *(const float4*)(A + (size_t)(row0 + aRow + 32 * i) * K + kn + aCol);
            #pragma unroll
            for (int i = 0; i < 4; i++)
                pb[i] = *(const float4*)(B + (size_t)(kn + bRow + 8 * i) * N + col0 + bCol);
        }

        #pragma unroll
        for (int ks = 0; ks < BK / 16; ks++) {
            int kk = ks * 16;
            uint32_t af[4][4];
            #pragma unroll
            for (int mt = 0; mt < 4; mt++)
                ldsm_x4(af[mt][0], af[mt][1], af[mt][2], af[mt][3],
                        as_u32 + 2u * ((wm + mt * 16 + lr) * AW + kk + lhi));
            uint32_t bf[4][2];
            #pragma unroll
            for (int nt2 = 0; nt2 < 2; nt2++) {
                uint32_t r0, r1, r2, r3;   // trans: (r0,r1)=n-lo, (r2,r3)=n-hi
                ldsm_x4_t(r0, r1, r2, r3,
                          bs_u32 + 2u * ((kk + lr) * BW + wn + nt2 * 16 + lhi));
                bf[2 * nt2][0] = r0;  bf[2 * nt2][1] = r1;
                bf[2 * nt2 + 1][0] = r2;  bf[2 * nt2 + 1][1] = r3;
            }
            #pragma unroll
            for (int mt = 0; mt < 4; mt++)
                #pragma unroll
                for (int nt = 0; nt < 4; nt++)
                    mma_f16(acc[mt][nt], af[mt][0], af[mt][1], af[mt][2], af[mt][3],
                            bf[nt][0], bf[nt][1]);
        }
        __syncthreads();
    }

    #pragma unroll
    for (int mt = 0; mt < 4; mt++) {
        int r = row0 + wm + mt * 16 + g;
        #pragma unroll
        for (int nt = 0; nt < 4; nt++) {
            int c = col0 + wn + nt * 8 + 2 * q;
            float bx = 0.f, by = 0.f;
            if (bias) { bx = bias[c]; by = bias[c + 1]; }
            float v0 = acc[mt][nt][0] + bx, v1 = acc[mt][nt][1] + by;
            float v2 = acc[mt][nt][2] + bx, v3 = acc[mt][nt][3] + by;
            if (out_half) {
                __half* Ch = (__half*)Cout;
                *(__half2*)(Ch + (size_t)r * N + c)       = __floats2half2_rn(v0, v1);
                *(__half2*)(Ch + (size_t)(r + 8) * N + c) = __floats2half2_rn(v2, v3);
            } else {
                float* Cf = (float*)Cout;
                *(float2*)(Cf + (size_t)r * N + c)       = make_float2(v0, v1);
                *(float2*)(Cf + (size_t)(r + 8) * N + c) = make_float2(v2, v3);
            }
        }
    }
}

// ---------------------------------------------------------------------------
// Flash attention (fp16 mma): block = (b, h, 64-row Q tile), 4 warps, KT=64.
// qkv is fp16 (pre-rounded by GEMM1): Q/K/V are pure cp.async byte copies,
// K/V double-buffered. SCALE applied on fp32 S registers (exact).
// All tiles stride 72 halves (144 B): ldmatrix (trans and non-trans)
// conflict-free. S B-frags: non-trans x4 on K[kv][d] -> pairs (r0,r2)/(r1,r3).
// PV B-frags: trans x4 on V[kv][d] -> pairs (r0,r1)/(r2,r3).
// smem 54 KB -> 4 CTAs/SM.
// ---------------------------------------------------------------------------
#define QT  64
#define KT  64
#define FW  72    // halves per row
#define TILE_H (64 * FW)
#define FLASH_SMEM_BYTES (6 * TILE_H * 2)

__global__ __launch_bounds__(128)
void flash_f16(const __half* __restrict__ qkv, float* __restrict__ out) {
    extern __shared__ __half smh[];
    __half* Qs    = smh;                     // [64][FW]
    __half* Ks[2] = { smh + TILE_H,  smh + 2 * TILE_H };
    __half* Vs[2] = { smh + 3 * TILE_H, smh + 4 * TILE_H };
    __half* Ps    = smh + 5 * TILE_H;

    int b  = blockIdx.z, h = blockIdx.y;
    int q0 = blockIdx.x * QT;
    int tid = threadIdx.x;
    int lane = tid & 31, wid = tid >> 5;
    int g = lane >> 2, qd = lane & 3;
    int m0 = wid * 16;
    uint32_t lr = lane & 15, lhi = (lane >> 4) * 8;

    uint32_t q_u32 = (uint32_t)__cvta_generic_to_shared(Qs);
    uint32_t k_u32[2] = { (uint32_t)__cvta_generic_to_shared(Ks[0]),
                          (uint32_t)__cvta_generic_to_shared(Ks[1]) };
    uint32_t v_u32[2] = { (uint32_t)__cvta_generic_to_shared(Vs[0]),
                          (uint32_t)__cvta_generic_to_shared(Vs[1]) };
    uint32_t p_u32 = (uint32_t)__cvta_generic_to_shared(Ps);

    uint32_t aoffQ = (m0 + lr) * FW + lhi;   // halves
    uint32_t boffK = lr * FW + lhi;

    const __half* base = qkv + (size_t)b * SEQ * QKVW;
    int hc = h * DH;

    // copy slots: row = tid>>1 (64 rows), halves offset = (tid&1)*32 + i*8
    int cr = tid >> 1, ch = (tid & 1) << 5;

    // prefetch Q + tile-0 K/V (one group)
    #pragma unroll
    for (int i = 0; i < 4; i++) {
        int off = ch + i * 8;
        const __half* qsrc = base + (size_t)(q0 + cr) * QKVW + hc + off;
        cp_async16(q_u32 + 2u * (cr * FW + off), qsrc);
        const __half* src = base + (size_t)cr * QKVW + hc + off;
        cp_async16(k_u32[0] + 2u * (cr * FW + off), src + DMODEL);
        cp_async16(v_u32[0] + 2u * (cr * FW + off), src + 2 * DMODEL);
    }
    cp_commit();

    float o[8][4] = {};
    float mr0 = -INFINITY, mr1 = -INFINITY, l0 = 0.f, l1 = 0.f;

    const int NT = SEQ / KT;   // 32
    for (int kt = 0; kt < NT; kt++) {
        int buf = kt & 1;
        cp_wait_all();
        __syncthreads();

        if (kt + 1 < NT) {
            int nbuf = buf ^ 1;
            int k0n = (kt + 1) * KT;
            #pragma unroll
            for (int i = 0; i < 4; i++) {
                int off = ch + i * 8;
                const __half* src = base + (size_t)(k0n + cr) * QKVW + hc + off;
                cp_async16(k_u32[nbuf] + 2u * (cr * FW + off), src + DMODEL);
                cp_async16(v_u32[nbuf] + 2u * (cr * FW + off), src + 2 * DMODEL);
            }
            cp_commit();
        }

        // S(16x64) = Qstrip @ K^T
        float s[8][4] = {};
        #pragma unroll
        for (int ks = 0; ks < 4; ks++) {
            int kk = ks * 16;
            uint32_t a0, a1, a2, a3;
            ldsm_x4(a0, a1, a2, a3, q_u32 + 2u * (aoffQ + kk));
            #pragma unroll
            for (int nt2 = 0; nt2 < 4; nt2++) {
                uint32_t b0, b1, b2, b3;   // non-trans: pairs (b0,b2),(b1,b3)
                ldsm_x4(b0, b1, b2, b3,
                        k_u32[buf] + 2u * (boffK + nt2 * 16 * FW + kk));
                mma_f16(s[2 * nt2    ], a0, a1, a2, a3, b0, b2);
                mma_f16(s[2 * nt2 + 1], a0, a1, a2, a3, b1, b3);
            }
        }

        // scale (fp32, exact 2^-3) then online softmax; quad-lane reduce
        float mx0 = -INFINITY, mx1 = -INFINITY;
        #pragma unroll
        for (int nt = 0; nt < 8; nt++) {
            s[nt][0] *= SCALE; s[nt][1] *= SCALE;
            s[nt][2] *= SCALE; s[nt][3] *= SCALE;
            mx0 = fmaxf(mx0, fmaxf(s[nt][0], s[nt][1]));
            mx1 = fmaxf(mx1, fmaxf(s[nt][2], s[nt][3]));
        }
        #pragma unroll
        for (int w = 1; w < 4; w <<= 1) {
            mx0 = fmaxf(mx0, __shfl_xor_sync(0xffffffffu, mx0, w));
            mx1 = fmaxf(mx1, __shfl_xor_sync(0xffffffffu, mx1, w));
        }
        float mn0 = fmaxf(mr0, mx0), mn1 = fmaxf(mr1, mx1);
        float al0 = __expf(mr0 - mn0), al1 = __expf(mr1 - mn1);
        mr0 = mn0; mr1 = mn1;

        float sum0 = 0.f, sum1 = 0.f;
        #pragma unroll
        for (int nt = 0; nt < 8; nt++) {
            s[nt][0] = __expf(s[nt][0] - mn0); sum0 += s[nt][0];
            s[nt][1] = __expf(s[nt][1] - mn0); sum0 += s[nt][1];
            s[nt][2] = __expf(s[nt][2] - mn1); sum1 += s[nt][2];
            s[nt][3] = __expf(s[nt][3] - mn1); sum1 += s[nt][3];
        }
        #pragma unroll
        for (int w = 1; w < 4; w <<= 1) {
            sum0 += __shfl_xor_sync(0xffffffffu, sum0, w);
            sum1 += __shfl_xor_sync(0xffffffffu, sum1, w);
        }
        l0 = l0 * al0 + sum0;
        l1 = l1 * al1 + sum1;

        // stage P as half2 (warp-private rows)
        #pragma unroll
        for (int nt = 0; nt < 8; nt++) {
            int c = nt * 8 + 2 * qd;
            *(__half2*)&Ps[(m0 + g    ) * FW + c] = __floats2half2_rn(s[nt][0], s[nt][1]);
            *(__half2*)&Ps[(m0 + g + 8) * FW + c] = __floats2half2_rn(s[nt][2], s[nt][3]);
        }
        __syncwarp();

        // O = O*alpha + P @ V
        #pragma unroll
        for (int nt = 0; nt < 8; nt++) {
            o[nt][0] *= al0; o[nt][1] *= al0;
            o[nt][2] *= al1; o[nt][3] *= al1;
        }
        #pragma unroll
        for (int ks = 0; ks < 4; ks++) {
            int kk = ks * 16;   // kv offset
            uint32_t a0, a1, a2, a3;
            ldsm_x4(a0, a1, a2, a3, p_u32 + 2u * (aoffQ - (m0 + lr) * FW
                                                 + (m0 + lr) * FW + kk));  // Ps same FW
            #pragma unroll
            for (int nt2 = 0; nt2 < 4; nt2++) {
                uint32_t b0, b1, b2, b3;   // trans: pairs (b0,b1),(b2,b3)
                ldsm_x4_t(b0, b1, b2, b3,
                          v_u32[buf] + 2u * ((kk + lr) * FW + nt2 * 16 + lhi));
                mma_f16(o[2 * nt2    ], a0, a1, a2, a3, b0, b1);
                mma_f16(o[2 * nt2 + 1], a0, a1, a2, a3, b2, b3);
            }
        }
    }

    // normalize + write 'b n (h d)' (fp32)
    float inv0 = 1.f / l0, inv1 = 1.f / l1;
    #pragma unroll
    for (int nt = 0; nt < 8; nt++) {
        int r = q0 + m0 + g;
        int c = hc + nt * 8 + 2 * qd;
        *(float2*)(out + (size_t)((size_t)b * SEQ + r) * DMODEL + c) =
            make_float2(o[nt][0] * inv0, o[nt][1] * inv0);
        *(float2*)(out + (size_t)((size_t)b * SEQ + r + 8) * DMODEL + c) =
            make_float2(o[nt][2] * inv1, o[nt][3] * inv1);
    }
}

// ---------------------------------------------------------------------------
extern "C" void kernel_launch(void* const* d_in, const int* in_sizes, int n_in,
                              void* d_out, int out_size) {
    const float* x     = (const float*)d_in[0];
    const float* W_qkv = (const float*)d_in[1];
    const float* W_out = (const float*)d_in[2];
    const float* b_out = (const float*)d_in[3];
    float* out = (float*)d_out;

    __half* qkv; cudaGetSymbolAddress((void**)&qkv,  g_qkv);
    float* attn; cudaGetSymbolAddress((void**)&attn, g_attn);

    cudaFuncSetAttribute(flash_f16,
                         cudaFuncAttributeMaxDynamicSharedMemorySize,
                         FLASH_SMEM_BYTES);

    const int M = BATCH * SEQ;  // 8192

    // 1) qkv = x @ W_qkv  (fp16 output)
    gemm_f16<<<dim3(QKVW / BN, M / BM), 256>>>(
        x, W_qkv, nullptr, qkv, M, QKVW, DMODEL, 1);

    // 2) attention per (b, h, q-tile)
    flash_f16<<<dim3(SEQ / QT, HEADS, BATCH), 128, FLASH_SMEM_BYTES>>>(
        qkv, attn);

    // 3) out = attn @ W_out + b_out  (fp32 output)
    gemm_f16<<<dim3(DMODEL / BN, M / BM), 256>>>(
        attn, W_out, b_out, out, M, DMODEL, DMODEL, 0);
}

// round 10
// speedup vs baseline: 2.0399x; 1.0169x over previous
#include <cuda_runtime.h>
#include <cuda_fp16.h>
#include <math.h>
#include <stdint.h>

#define HEADS   12
#define DH      64
#define SEQ     2048
#define BATCH   4
#define DMODEL  768
#define QKVW    2304      // 3 * 768
#define SCALE   0.125f    // 64^-0.5

// Scratch (device globals; no allocations allowed)
__device__ __half g_xh  [(size_t)BATCH * SEQ * DMODEL];   // x in fp16
__device__ __half g_wqh [(size_t)DMODEL * QKVW];          // W_qkv in fp16
__device__ __half g_woh [(size_t)DMODEL * DMODEL];        // W_out in fp16
__device__ __half g_qkv [(size_t)BATCH * SEQ * QKVW];     // qkv (fp16)
__device__ __half g_attn[(size_t)BATCH * SEQ * DMODEL];   // attn out (fp16)

// ---------------------------------------------------------------------------
// helpers
// ---------------------------------------------------------------------------
__device__ __forceinline__ void mma_f16(float c[4],
                                        uint32_t a0, uint32_t a1,
                                        uint32_t a2, uint32_t a3,
                                        uint32_t b0, uint32_t b1) {
    asm volatile(
        "mma.sync.aligned.m16n8k16.row.col.f32.f16.f16.f32 "
        "{%0,%1,%2,%3}, {%4,%5,%6,%7}, {%8,%9}, {%0,%1,%2,%3};\n"
        : "+f"(c[0]), "+f"(c[1]), "+f"(c[2]), "+f"(c[3])
        : "r"(a0), "r"(a1), "r"(a2), "r"(a3), "r"(b0), "r"(b1));
}

__device__ __forceinline__ void ldsm_x4(uint32_t& r0, uint32_t& r1,
                                        uint32_t& r2, uint32_t& r3,
                                        uint32_t addr) {
    asm volatile(
        "ldmatrix.sync.aligned.m8n8.x4.shared.b16 {%0,%1,%2,%3}, [%4];"
        : "=r"(r0), "=r"(r1), "=r"(r2), "=r"(r3) : "r"(addr));
}

__device__ __forceinline__ void ldsm_x4_t(uint32_t& r0, uint32_t& r1,
                                          uint32_t& r2, uint32_t& r3,
                                          uint32_t addr) {
    asm volatile(
        "ldmatrix.sync.aligned.m8n8.x4.trans.shared.b16 {%0,%1,%2,%3}, [%4];"
        : "=r"(r0), "=r"(r1), "=r"(r2), "=r"(r3) : "r"(addr));
}

__device__ __forceinline__ void cp_async16(uint32_t dst_smem, const void* src) {
    asm volatile("cp.async.cg.shared.global [%0], [%1], 16;"
                 :: "r"(dst_smem), "l"(src));
}
__device__ __forceinline__ void cp_commit() {
    asm volatile("cp.async.commit_group;");
}
__device__ __forceinline__ void cp_wait_all() {
    asm volatile("cp.async.wait_group 0;");
}

__device__ __forceinline__ uint32_t pack_h2(float lo, float hi) {
    __half2 h = __floats2half2_rn(lo, hi);
    return *reinterpret_cast<uint32_t*>(&h);
}

// ---------------------------------------------------------------------------
// fp32 -> fp16 elementwise (n % 4 == 0)
// ---------------------------------------------------------------------------
__global__ __launch_bounds__(256)
void f32_to_f16(const float* __restrict__ src, __half* __restrict__ dst, int n) {
    int i = (blockIdx.x * 256 + threadIdx.x) * 4;
    if (i < n) {
        float4 v = *(const float4*)(src + i);
        *(__half2*)(dst + i)     = __floats2half2_rn(v.x, v.y);
        *(__half2*)(dst + i + 2) = __floats2half2_rn(v.z, v.w);
    }
}

// ---------------------------------------------------------------------------
// GEMM (fp16 in, fp32 accum): C = A @ B (+bias). A[M,K], B[K,N] fp16
// row-major. 128x128 tile, BK=32, 256 thr = 8 warps, warp tile 64x32.
// SYNCHRONOUS round-8 structure (store staged regs -> sync -> prefetch
// next via plain uint4 LDG -> compute -> sync). No cp.async, no cvt.
// A stride 40h, B stride 136h: ldmatrix conflict-free.
// ---------------------------------------------------------------------------
#define BM 128
#define BN 128
#define BK 32
#define AW 40     // halves
#define BW 136    // halves

__global__ __launch_bounds__(256)
void gemm_f16(const __half* __restrict__ A, const __half* __restrict__ B,
              const float* __restrict__ bias, void* __restrict__ Cout,
              int M, int N, int K, int out_half) {
    __shared__ __half As[BM * AW];
    __shared__ __half Bs[BK * BW];

    int tid  = threadIdx.x;
    int lane = tid & 31, wid = tid >> 5;
    int wm = (wid >> 2) * 64;
    int wn = (wid & 3) * 32;
    int g  = lane >> 2, q = lane & 3;
    uint32_t lr = lane & 15, lhi = (lane >> 4) * 8;   // halves

    uint32_t as_u32 = (uint32_t)__cvta_generic_to_shared(As);
    uint32_t bs_u32 = (uint32_t)__cvta_generic_to_shared(Bs);

    int row0 = blockIdx.y * BM, col0 = blockIdx.x * BN;

    // staging slots: A 128 rows x 32h (2 thr/row, 2 x uint4);
    //                B 32 rows x 128h (8 thr/row, 2 x uint4)
    int ar = tid >> 1, ac = (tid & 1) << 4;
    int br = tid >> 3, bc = (tid & 7) << 4;

    float acc[4][4][4] = {};
    uint4 pa0, pa1, pb0, pb1;

    pa0 = *(const uint4*)(A + (size_t)(row0 + ar) * K + ac);
    pa1 = *(const uint4*)(A + (size_t)(row0 + ar) * K + ac + 8);
    pb0 = *(const uint4*)(B + (size_t)br * N + col0 + bc);
    pb1 = *(const uint4*)(B + (size_t)br * N + col0 + bc + 8);

    for (int k0 = 0; k0 < K; k0 += BK) {
        *(uint4*)&As[ar * AW + ac]     = pa0;
        *(uint4*)&As[ar * AW + ac + 8] = pa1;
        *(uint4*)&Bs[br * BW + bc]     = pb0;
        *(uint4*)&Bs[br * BW + bc + 8] = pb1;
        __syncthreads();

        int kn = k0 + BK;
        if (kn < K) {
            pa0 = *(const uint4*)(A + (size_t)(row0 + ar) * K + kn + ac);
            pa1 = *(const uint4*)(A + (size_t)(row0 + ar) * K + kn + ac + 8);
            pb0 = *(const uint4*)(B + (size_t)(kn + br) * N + col0 + bc);
            pb1 = *(const uint4*)(B + (size_t)(kn + br) * N + col0 + bc + 8);
        }

        #pragma unroll
        for (int ks = 0; ks < BK / 16; ks++) {
            int kk = ks * 16;
            uint32_t af[4][4];
            #pragma unroll
            for (int mt = 0; mt < 4; mt++)
                ldsm_x4(af[mt][0], af[mt][1], af[mt][2], af[mt][3],
                        as_u32 + 2u * ((wm + mt * 16 + lr) * AW + kk + lhi));
            uint32_t bf[4][2];
            #pragma unroll
            for (int nt2 = 0; nt2 < 2; nt2++) {
                uint32_t r0, r1, r2, r3;   // trans: (r0,r1)=n-lo8, (r2,r3)=n-hi8
                ldsm_x4_t(r0, r1, r2, r3,
                          bs_u32 + 2u * ((kk + lr) * BW + wn + nt2 * 16 + lhi));
                bf[2 * nt2][0] = r0;      bf[2 * nt2][1] = r1;
                bf[2 * nt2 + 1][0] = r2;  bf[2 * nt2 + 1][1] = r3;
            }
            #pragma unroll
            for (int mt = 0; mt < 4; mt++)
                #pragma unroll
                for (int nt = 0; nt < 4; nt++)
                    mma_f16(acc[mt][nt], af[mt][0], af[mt][1], af[mt][2], af[mt][3],
                            bf[nt][0], bf[nt][1]);
        }
        __syncthreads();
    }

    #pragma unroll
    for (int mt = 0; mt < 4; mt++) {
        int r = row0 + wm + mt * 16 + g;
        #pragma unroll
        for (int nt = 0; nt < 4; nt++) {
            int c = col0 + wn + nt * 8 + 2 * q;
            float bx = 0.f, by = 0.f;
            if (bias) { bx = bias[c]; by = bias[c + 1]; }
            float v0 = acc[mt][nt][0] + bx, v1 = acc[mt][nt][1] + by;
            float v2 = acc[mt][nt][2] + bx, v3 = acc[mt][nt][3] + by;
            if (out_half) {
                __half* Ch = (__half*)Cout;
                *(__half2*)(Ch + (size_t)r * N + c)       = __floats2half2_rn(v0, v1);
                *(__half2*)(Ch + (size_t)(r + 8) * N + c) = __floats2half2_rn(v2, v3);
            } else {
                float* Cf = (float*)Cout;
                *(float2*)(Cf + (size_t)r * N + c)       = make_float2(v0, v1);
                *(float2*)(Cf + (size_t)(r + 8) * N + c) = make_float2(v2, v3);
            }
        }
    }
}

// ---------------------------------------------------------------------------
// Flash attention (fp16 mma): round-8 proven structure (KT=64, 4 warps,
// cp.async double-buffered K/V), PLUS: P never touches smem — the S
// C-fragments ARE the PV A-fragments (packed to half2 in registers).
// smem 45 KB (Q + 2K + 2V).
// ---------------------------------------------------------------------------
#define QT  64
#define KT  64
#define FW  72    // halves per row
#define TILE_H (64 * FW)
#define FLASH_SMEM_BYTES (5 * TILE_H * 2)

__global__ __launch_bounds__(128)
void flash_f16(const __half* __restrict__ qkv, __half* __restrict__ out) {
    extern __shared__ __half smh[];
    uint32_t q_u32 = (uint32_t)__cvta_generic_to_shared(smh);
    uint32_t k_u32[2] = { q_u32 + 2u * TILE_H,     q_u32 + 2u * 2 * TILE_H };
    uint32_t v_u32[2] = { q_u32 + 2u * 3 * TILE_H, q_u32 + 2u * 4 * TILE_H };

    int b  = blockIdx.z, h = blockIdx.y;
    int q0 = blockIdx.x * QT;
    int tid = threadIdx.x;
    int lane = tid & 31, wid = tid >> 5;
    int g = lane >> 2, qd = lane & 3;
    int m0 = wid * 16;
    uint32_t lr = lane & 15, lhi = (lane >> 4) * 8;

    uint32_t aoffQ = (m0 + lr) * FW + lhi;
    uint32_t boffK = lr * FW + lhi;

    const __half* base = qkv + (size_t)b * SEQ * QKVW;
    int hc = h * DH;

    int cr = tid >> 1, ch = (tid & 1) << 5;

    #pragma unroll
    for (int i = 0; i < 4; i++) {
        int off = ch + i * 8;
        const __half* qsrc = base + (size_t)(q0 + cr) * QKVW + hc + off;
        cp_async16(q_u32 + 2u * (cr * FW + off), qsrc);
        const __half* src = base + (size_t)cr * QKVW + hc + off;
        cp_async16(k_u32[0] + 2u * (cr * FW + off), src + DMODEL);
        cp_async16(v_u32[0] + 2u * (cr * FW + off), src + 2 * DMODEL);
    }
    cp_commit();

    float o[8][4] = {};
    float mr0 = -INFINITY, mr1 = -INFINITY, l0 = 0.f, l1 = 0.f;

    const int NT = SEQ / KT;   // 32
    for (int kt = 0; kt < NT; kt++) {
        int buf = kt & 1;
        cp_wait_all();
        __syncthreads();

        if (kt + 1 < NT) {
            int nbuf = buf ^ 1;
            int k0n = (kt + 1) * KT;
            #pragma unroll
            for (int i = 0; i < 4; i++) {
                int off = ch + i * 8;
                const __half* src = base + (size_t)(k0n + cr) * QKVW + hc + off;
                cp_async16(k_u32[nbuf] + 2u * (cr * FW + off), src + DMODEL);
                cp_async16(v_u32[nbuf] + 2u * (cr * FW + off), src + 2 * DMODEL);
            }
            cp_commit();
        }

        // S(16x64) = Qstrip @ K^T
        float s[8][4] = {};
        #pragma unroll
        for (int ks = 0; ks < 4; ks++) {
            int kk = ks * 16;
            uint32_t a0, a1, a2, a3;
            ldsm_x4(a0, a1, a2, a3, q_u32 + 2u * (aoffQ + kk));
            #pragma unroll
            for (int nt2 = 0; nt2 < 4; nt2++) {
                uint32_t b0, b1, b2, b3;   // non-trans: pairs (b0,b2),(b1,b3)
                ldsm_x4(b0, b1, b2, b3,
                        k_u32[buf] + 2u * (boffK + nt2 * 16 * FW + kk));
                mma_f16(s[2 * nt2    ], a0, a1, a2, a3, b0, b2);
                mma_f16(s[2 * nt2 + 1], a0, a1, a2, a3, b1, b3);
            }
        }

        // scale + online softmax (fp32, quad-lane reduce)
        float mx0 = -INFINITY, mx1 = -INFINITY;
        #pragma unroll
        for (int nt = 0; nt < 8; nt++) {
            s[nt][0] *= SCALE; s[nt][1] *= SCALE;
            s[nt][2] *= SCALE; s[nt][3] *= SCALE;
            mx0 = fmaxf(mx0, fmaxf(s[nt][0], s[nt][1]));
            mx1 = fmaxf(mx1, fmaxf(s[nt][2], s[nt][3]));
        }
        #pragma unroll
        for (int w = 1; w < 4; w <<= 1) {
            mx0 = fmaxf(mx0, __shfl_xor_sync(0xffffffffu, mx0, w));
            mx1 = fmaxf(mx1, __shfl_xor_sync(0xffffffffu, mx1, w));
        }
        float mn0 = fmaxf(mr0, mx0), mn1 = fmaxf(mr1, mx1);
        float al0 = __expf(mr0 - mn0), al1 = __expf(mr1 - mn1);
        mr0 = mn0; mr1 = mn1;

        float sum0 = 0.f, sum1 = 0.f;
        #pragma unroll
        for (int nt = 0; nt < 8; nt++) {
            s[nt][0] = __expf(s[nt][0] - mn0); sum0 += s[nt][0];
            s[nt][1] = __expf(s[nt][1] - mn0); sum0 += s[nt][1];
            s[nt][2] = __expf(s[nt][2] - mn1); sum1 += s[nt][2];
            s[nt][3] = __expf(s[nt][3] - mn1); sum1 += s[nt][3];
        }
        #pragma unroll
        for (int w = 1; w < 4; w <<= 1) {
            sum0 += __shfl_xor_sync(0xffffffffu, sum0, w);
            sum1 += __shfl_xor_sync(0xffffffffu, sum1, w);
        }
        l0 = l0 * al0 + sum0;
        l1 = l1 * al1 + sum1;

        // O = O*alpha + P @ V : P A-fragments come straight from S C-frags
        #pragma unroll
        for (int nt = 0; nt < 8; nt++) {
            o[nt][0] *= al0; o[nt][1] *= al0;
            o[nt][2] *= al1; o[nt][3] *= al1;
        }
        #pragma unroll
        for (int c2 = 0; c2 < 4; c2++) {
            int kk = c2 * 16;   // kv offset
            uint32_t a0 = pack_h2(s[2 * c2    ][0], s[2 * c2    ][1]);
            uint32_t a1 = pack_h2(s[2 * c2    ][2], s[2 * c2    ][3]);
            uint32_t a2 = pack_h2(s[2 * c2 + 1][0], s[2 * c2 + 1][1]);
            uint32_t a3 = pack_h2(s[2 * c2 + 1][2], s[2 * c2 + 1][3]);
            #pragma unroll
            for (int nt2 = 0; nt2 < 4; nt2++) {
                uint32_t b0, b1, b2, b3;   // trans: pairs (b0,b1),(b2,b3)
                ldsm_x4_t(b0, b1, b2, b3,
                          v_u32[buf] + 2u * ((kk + lr) * FW + nt2 * 16 + lhi));
                mma_f16(o[2 * nt2    ], a0, a1, a2, a3, b0, b1);
                mma_f16(o[2 * nt2 + 1], a0, a1, a2, a3, b2, b3);
            }
        }
    }

    // normalize + write 'b n (h d)' as fp16
    float inv0 = 1.f / l0, inv1 = 1.f / l1;
    #pragma unroll
    for (int nt = 0; nt < 8; nt++) {
        int r = q0 + m0 + g;
        int c = hc + nt * 8 + 2 * qd;
        *(__half2*)(out + (size_t)((size_t)b * SEQ + r) * DMODEL + c) =
            __floats2half2_rn(o[nt][0] * inv0, o[nt][1] * inv0);
        *(__half2*)(out + (size_t)((size_t)b * SEQ + r + 8) * DMODEL + c) =
            __floats2half2_rn(o[nt][2] * inv1, o[nt][3] * inv1);
    }
}

// ---------------------------------------------------------------------------
extern "C" void kernel_launch(void* const* d_in, const int* in_sizes, int n_in,
                              void* d_out, int out_size) {
    const float* x     = (const float*)d_in[0];
    const float* W_qkv = (const float*)d_in[1];
    const float* W_out = (const float*)d_in[2];
    const float* b_out = (const float*)d_in[3];
    float* out = (float*)d_out;

    __half *xh, *wqh, *woh, *qkv, *attn;
    cudaGetSymbolAddress((void**)&xh,   g_xh);
    cudaGetSymbolAddress((void**)&wqh,  g_wqh);
    cudaGetSymbolAddress((void**)&woh,  g_woh);
    cudaGetSymbolAddress((void**)&qkv,  g_qkv);
    cudaGetSymbolAddress((void**)&attn, g_attn);

    cudaFuncSetAttribute(flash_f16,
                         cudaFuncAttributeMaxDynamicSharedMemorySize,
                         FLASH_SMEM_BYTES);

    const int M = BATCH * SEQ;  // 8192
    const int NX = M * DMODEL, NWQ = DMODEL * QKVW, NWO = DMODEL * DMODEL;

    // 0) fp16 pre-conversion
    f32_to_f16<<<NX  / 1024, 256>>>(x,     xh,  NX);
    f32_to_f16<<<NWQ / 1024, 256>>>(W_qkv, wqh, NWQ);
    f32_to_f16<<<NWO / 1024, 256>>>(W_out, woh, NWO);

    // 1) qkv = x @ W_qkv  (fp16 out)
    gemm_f16<<<dim3(QKVW / BN, M / BM), 256>>>(
        xh, wqh, nullptr, qkv, M, QKVW, DMODEL, 1);

    // 2) attention (fp16 out)
    flash_f16<<<dim3(SEQ / QT, HEADS, BATCH), 128, FLASH_SMEM_BYTES>>>(
        qkv, attn);

    // 3) out = attn @ W_out + b_out  (fp32 out)
    gemm_f16<<<dim3(DMODEL / BN, M / BM), 256>>>(
        attn, woh, b_out, out, M, DMODEL, DMODEL, 0);
}

// round 11
// speedup vs baseline: 2.0996x; 1.0293x over previous
#include <cuda_runtime.h>
#include <cuda_fp16.h>
#include <math.h>
#include <stdint.h>

#define HEADS   12
#define DH      64
#define SEQ     2048
#define BATCH   4
#define DMODEL  768
#define QKVW    2304      // 3 * 768
// softmax scale folded with log2(e): exp(x*SCALE) = exp2(x * SCL2)
#define SCL2    0.1803368801111244f   // 0.125 * log2(e)

// Scratch (device globals; no allocations allowed)
__device__ __half g_xh  [(size_t)BATCH * SEQ * DMODEL];
__device__ __half g_wqh [(size_t)DMODEL * QKVW];
__device__ __half g_woh [(size_t)DMODEL * DMODEL];
__device__ __half g_qkv [(size_t)BATCH * SEQ * QKVW];
__device__ __half g_attn[(size_t)BATCH * SEQ * DMODEL];

// ---------------------------------------------------------------------------
// helpers
// ---------------------------------------------------------------------------
__device__ __forceinline__ void mma_f16(float c[4],
                                        uint32_t a0, uint32_t a1,
                                        uint32_t a2, uint32_t a3,
                                        uint32_t b0, uint32_t b1) {
    asm volatile(
        "mma.sync.aligned.m16n8k16.row.col.f32.f16.f16.f32 "
        "{%0,%1,%2,%3}, {%4,%5,%6,%7}, {%8,%9}, {%0,%1,%2,%3};\n"
        : "+f"(c[0]), "+f"(c[1]), "+f"(c[2]), "+f"(c[3])
        : "r"(a0), "r"(a1), "r"(a2), "r"(a3), "r"(b0), "r"(b1));
}

__device__ __forceinline__ void ldsm_x4(uint32_t& r0, uint32_t& r1,
                                        uint32_t& r2, uint32_t& r3,
                                        uint32_t addr) {
    asm volatile(
        "ldmatrix.sync.aligned.m8n8.x4.shared.b16 {%0,%1,%2,%3}, [%4];"
        : "=r"(r0), "=r"(r1), "=r"(r2), "=r"(r3) : "r"(addr));
}

__device__ __forceinline__ void ldsm_x4_t(uint32_t& r0, uint32_t& r1,
                                          uint32_t& r2, uint32_t& r3,
                                          uint32_t addr) {
    asm volatile(
        "ldmatrix.sync.aligned.m8n8.x4.trans.shared.b16 {%0,%1,%2,%3}, [%4];"
        : "=r"(r0), "=r"(r1), "=r"(r2), "=r"(r3) : "r"(addr));
}

__device__ __forceinline__ void cp_async16(uint32_t dst_smem, const void* src) {
    asm volatile("cp.async.cg.shared.global [%0], [%1], 16;"
                 :: "r"(dst_smem), "l"(src));
}
__device__ __forceinline__ void cp_commit() {
    asm volatile("cp.async.commit_group;");
}
__device__ __forceinline__ void cp_wait_all() {
    asm volatile("cp.async.wait_group 0;");
}

__device__ __forceinline__ uint32_t pack_h2(float lo, float hi) {
    __half2 h = __floats2half2_rn(lo, hi);
    return *reinterpret_cast<uint32_t*>(&h);
}

// ---------------------------------------------------------------------------
// fp32 -> fp16 elementwise (n % 4 == 0)
// ---------------------------------------------------------------------------
__global__ __launch_bounds__(256)
void f32_to_f16(const float* __restrict__ src, __half* __restrict__ dst, int n) {
    int i = (blockIdx.x * 256 + threadIdx.x) * 4;
    if (i < n) {
        float4 v = *(const float4*)(src + i);
        *(__half2*)(dst + i)     = __floats2half2_rn(v.x, v.y);
        *(__half2*)(dst + i + 2) = __floats2half2_rn(v.z, v.w);
    }
}

// ---------------------------------------------------------------------------
// GEMM (fp16 in, fp32 accum): UNCHANGED round-10 structure (134us known-good).
// ---------------------------------------------------------------------------
#define BM 128
#define BN 128
#define BK 32
#define AW 40     // halves
#define BW 136    // halves

__global__ __launch_bounds__(256)
void gemm_f16(const __half* __restrict__ A, const __half* __restrict__ B,
              const float* __restrict__ bias, void* __restrict__ Cout,
              int M, int N, int K, int out_half) {
    __shared__ __half As[BM * AW];
    __shared__ __half Bs[BK * BW];

    int tid  = threadIdx.x;
    int lane = tid & 31, wid = tid >> 5;
    int wm = (wid >> 2) * 64;
    int wn = (wid & 3) * 32;
    int g  = lane >> 2, q = lane & 3;
    uint32_t lr = lane & 15, lhi = (lane >> 4) * 8;

    uint32_t as_u32 = (uint32_t)__cvta_generic_to_shared(As);
    uint32_t bs_u32 = (uint32_t)__cvta_generic_to_shared(Bs);

    int row0 = blockIdx.y * BM, col0 = blockIdx.x * BN;

    int ar = tid >> 1, ac = (tid & 1) << 4;
    int br = tid >> 3, bc = (tid & 7) << 4;

    float acc[4][4][4] = {};
    uint4 pa0, pa1, pb0, pb1;

    pa0 = *(const uint4*)(A + (size_t)(row0 + ar) * K + ac);
    pa1 = *(const uint4*)(A + (size_t)(row0 + ar) * K + ac + 8);
    pb0 = *(const uint4*)(B + (size_t)br * N + col0 + bc);
    pb1 = *(const uint4*)(B + (size_t)br * N + col0 + bc + 8);

    for (int k0 = 0; k0 < K; k0 += BK) {
        *(uint4*)&As[ar * AW + ac]     = pa0;
        *(uint4*)&As[ar * AW + ac + 8] = pa1;
        *(uint4*)&Bs[br * BW + bc]     = pb0;
        *(uint4*)&Bs[br * BW + bc + 8] = pb1;
        __syncthreads();

        int kn = k0 + BK;
        if (kn < K) {
            pa0 = *(const uint4*)(A + (size_t)(row0 + ar) * K + kn + ac);
            pa1 = *(const uint4*)(A + (size_t)(row0 + ar) * K + kn + ac + 8);
            pb0 = *(const uint4*)(B + (size_t)(kn + br) * N + col0 + bc);
            pb1 = *(const uint4*)(B + (size_t)(kn + br) * N + col0 + bc + 8);
        }

        #pragma unroll
        for (int ks = 0; ks < BK / 16; ks++) {
            int kk = ks * 16;
            uint32_t af[4][4];
            #pragma unroll
            for (int mt = 0; mt < 4; mt++)
                ldsm_x4(af[mt][0], af[mt][1], af[mt][2], af[mt][3],
                        as_u32 + 2u * ((wm + mt * 16 + lr) * AW + kk + lhi));
            uint32_t bf[4][2];
            #pragma unroll
            for (int nt2 = 0; nt2 < 2; nt2++) {
                uint32_t r0, r1, r2, r3;
                ldsm_x4_t(r0, r1, r2, r3,
                          bs_u32 + 2u * ((kk + lr) * BW + wn + nt2 * 16 + lhi));
                bf[2 * nt2][0] = r0;      bf[2 * nt2][1] = r1;
                bf[2 * nt2 + 1][0] = r2;  bf[2 * nt2 + 1][1] = r3;
            }
            #pragma unroll
            for (int mt = 0; mt < 4; mt++)
                #pragma unroll
                for (int nt = 0; nt < 4; nt++)
                    mma_f16(acc[mt][nt], af[mt][0], af[mt][1], af[mt][2], af[mt][3],
                            bf[nt][0], bf[nt][1]);
        }
        __syncthreads();
    }

    #pragma unroll
    for (int mt = 0; mt < 4; mt++) {
        int r = row0 + wm + mt * 16 + g;
        #pragma unroll
        for (int nt = 0; nt < 4; nt++) {
            int c = col0 + wn + nt * 8 + 2 * q;
            float bx = 0.f, by = 0.f;
            if (bias) { bx = bias[c]; by = bias[c + 1]; }
            float v0 = acc[mt][nt][0] + bx, v1 = acc[mt][nt][1] + by;
            float v2 = acc[mt][nt][2] + bx, v3 = acc[mt][nt][3] + by;
            if (out_half) {
                __half* Ch = (__half*)Cout;
                *(__half2*)(Ch + (size_t)r * N + c)       = __floats2half2_rn(v0, v1);
                *(__half2*)(Ch + (size_t)(r + 8) * N + c) = __floats2half2_rn(v2, v3);
            } else {
                float* Cf = (float*)Cout;
                *(float2*)(Cf + (size_t)r * N + c)       = make_float2(v0, v1);
                *(float2*)(Cf + (size_t)(r + 8) * N + c) = make_float2(v2, v3);
            }
        }
    }
}

// ---------------------------------------------------------------------------
// Flash attention (fp16 mma): block = (b, h, 128-row Q tile), 4 warps.
// Each warp owns TWO 16-row strips (rows wid*16 and 64+wid*16): K/V
// B-fragments ldmatrix'd once per tile and reused by both strips.
// P register-resident (S C-frags are PV A-frags). exp2-domain softmax.
// cp.async double-buffered K/V. smem 54 KB.
// ---------------------------------------------------------------------------
#define QT  128
#define KT  64
#define FW  72    // halves per row
#define QTILE_H (QT * FW)
#define KTILE_H (KT * FW)
#define FLASH_SMEM_BYTES ((QTILE_H + 4 * KTILE_H) * 2)

__global__ __launch_bounds__(128)
void flash_f16(const __half* __restrict__ qkv, __half* __restrict__ out) {
    extern __shared__ __half smh[];
    uint32_t q_u32 = (uint32_t)__cvta_generic_to_shared(smh);
    uint32_t k_u32[2] = { q_u32 + 2u * QTILE_H,
                          q_u32 + 2u * (QTILE_H + KTILE_H) };
    uint32_t v_u32[2] = { q_u32 + 2u * (QTILE_H + 2 * KTILE_H),
                          q_u32 + 2u * (QTILE_H + 3 * KTILE_H) };

    int b  = blockIdx.z, h = blockIdx.y;
    int q0 = blockIdx.x * QT;
    int tid = threadIdx.x;
    int lane = tid & 31, wid = tid >> 5;
    int g = lane >> 2, qd = lane & 3;
    int m0 = wid * 16;
    uint32_t lr = lane & 15, lhi = (lane >> 4) * 8;

    uint32_t boffK = lr * FW + lhi;

    const __half* base = qkv + (size_t)b * SEQ * QKVW;
    int hc = h * DH;

    int cr = tid >> 1, ch = (tid & 1) << 5;

    // prefetch Q (128 rows) + tile-0 K/V (64 rows each)
    #pragma unroll
    for (int i2 = 0; i2 < 2; i2++) {
        int row = cr + 64 * i2;
        #pragma unroll
        for (int i = 0; i < 4; i++) {
            int off = ch + i * 8;
            cp_async16(q_u32 + 2u * (row * FW + off),
                       base + (size_t)(q0 + row) * QKVW + hc + off);
        }
    }
    #pragma unroll
    for (int i = 0; i < 4; i++) {
        int off = ch + i * 8;
        const __half* src = base + (size_t)cr * QKVW + hc + off;
        cp_async16(k_u32[0] + 2u * (cr * FW + off), src + DMODEL);
        cp_async16(v_u32[0] + 2u * (cr * FW + off), src + 2 * DMODEL);
    }
    cp_commit();

    float o[2][8][4] = {};
    uint32_t ap[2][16];
    float mr[2][2] = {{-INFINITY, -INFINITY}, {-INFINITY, -INFINITY}};
    float li[2][2] = {{0.f, 0.f}, {0.f, 0.f}};
    float al[2][2];

    const int NT = SEQ / KT;   // 32
    for (int kt = 0; kt < NT; kt++) {
        int buf = kt & 1;
        cp_wait_all();
        __syncthreads();

        if (kt + 1 < NT) {
            int nbuf = buf ^ 1;
            int k0n = (kt + 1) * KT;
            #pragma unroll
            for (int i = 0; i < 4; i++) {
                int off = ch + i * 8;
                const __half* src = base + (size_t)(k0n + cr) * QKVW + hc + off;
                cp_async16(k_u32[nbuf] + 2u * (cr * FW + off), src + DMODEL);
                cp_async16(v_u32[nbuf] + 2u * (cr * FW + off), src + 2 * DMODEL);
            }
            cp_commit();
        }

        // per strip: S = Qstrip @ K^T, softmax, pack P
        #pragma unroll
        for (int st = 0; st < 2; st++) {
            uint32_t aoffQ = (st * 64 + m0 + lr) * FW + lhi;

            float s[8][4] = {};
            #pragma unroll
            for (int ks = 0; ks < 4; ks++) {
                int kk = ks * 16;
                uint32_t a0, a1, a2, a3;
                ldsm_x4(a0, a1, a2, a3, q_u32 + 2u * (aoffQ + kk));
                #pragma unroll
                for (int nt2 = 0; nt2 < 4; nt2++) {
                    uint32_t b0, b1, b2, b3;   // non-trans: pairs (b0,b2),(b1,b3)
                    ldsm_x4(b0, b1, b2, b3,
                            k_u32[buf] + 2u * (boffK + nt2 * 16 * FW + kk));
                    mma_f16(s[2 * nt2    ], a0, a1, a2, a3, b0, b2);
                    mma_f16(s[2 * nt2 + 1], a0, a1, a2, a3, b1, b3);
                }
            }

            // exp2-domain online softmax (SCALE*log2e folded into SCL2)
            float mx0 = -INFINITY, mx1 = -INFINITY;
            #pragma unroll
            for (int nt = 0; nt < 8; nt++) {
                s[nt][0] *= SCL2; s[nt][1] *= SCL2;
                s[nt][2] *= SCL2; s[nt][3] *= SCL2;
                mx0 = fmaxf(mx0, fmaxf(s[nt][0], s[nt][1]));
                mx1 = fmaxf(mx1, fmaxf(s[nt][2], s[nt][3]));
            }
            #pragma unroll
            for (int w = 1; w < 4; w <<= 1) {
                mx0 = fmaxf(mx0, __shfl_xor_sync(0xffffffffu, mx0, w));
                mx1 = fmaxf(mx1, __shfl_xor_sync(0xffffffffu, mx1, w));
            }
            float mn0 = fmaxf(mr[st][0], mx0), mn1 = fmaxf(mr[st][1], mx1);
            al[st][0] = exp2f(mr[st][0] - mn0);
            al[st][1] = exp2f(mr[st][1] - mn1);
            mr[st][0] = mn0; mr[st][1] = mn1;

            float sum0 = 0.f, sum1 = 0.f;
            #pragma unroll
            for (int nt = 0; nt < 8; nt++) {
                s[nt][0] = exp2f(s[nt][0] - mn0); sum0 += s[nt][0];
                s[nt][1] = exp2f(s[nt][1] - mn0); sum0 += s[nt][1];
                s[nt][2] = exp2f(s[nt][2] - mn1); sum1 += s[nt][2];
                s[nt][3] = exp2f(s[nt][3] - mn1); sum1 += s[nt][3];
            }
            #pragma unroll
            for (int w = 1; w < 4; w <<= 1) {
                sum0 += __shfl_xor_sync(0xffffffffu, sum0, w);
                sum1 += __shfl_xor_sync(0xffffffffu, sum1, w);
            }
            li[st][0] = li[st][0] * al[st][0] + sum0;
            li[st][1] = li[st][1] * al[st][1] + sum1;

            // pack P into PV A-fragments (register-resident)
            #pragma unroll
            for (int c2 = 0; c2 < 4; c2++) {
                ap[st][c2 * 4 + 0] = pack_h2(s[2 * c2    ][0], s[2 * c2    ][1]);
                ap[st][c2 * 4 + 1] = pack_h2(s[2 * c2    ][2], s[2 * c2    ][3]);
                ap[st][c2 * 4 + 2] = pack_h2(s[2 * c2 + 1][0], s[2 * c2 + 1][1]);
                ap[st][c2 * 4 + 3] = pack_h2(s[2 * c2 + 1][2], s[2 * c2 + 1][3]);
            }

            // rescale O strip
            #pragma unroll
            for (int nt = 0; nt < 8; nt++) {
                o[st][nt][0] *= al[st][0]; o[st][nt][1] *= al[st][0];
                o[st][nt][2] *= al[st][1]; o[st][nt][3] *= al[st][1];
            }
        }

        // PV: V B-frags loaded once, reused by both strips
        #pragma unroll
        for (int c2 = 0; c2 < 4; c2++) {
            int kk = c2 * 16;
            #pragma unroll
            for (int nt2 = 0; nt2 < 4; nt2++) {
                uint32_t b0, b1, b2, b3;   // trans: pairs (b0,b1),(b2,b3)
                ldsm_x4_t(b0, b1, b2, b3,
                          v_u32[buf] + 2u * ((kk + lr) * FW + nt2 * 16 + lhi));
                #pragma unroll
                for (int st = 0; st < 2; st++) {
                    mma_f16(o[st][2 * nt2    ], ap[st][c2*4+0], ap[st][c2*4+1],
                            ap[st][c2*4+2], ap[st][c2*4+3], b0, b1);
                    mma_f16(o[st][2 * nt2 + 1], ap[st][c2*4+0], ap[st][c2*4+1],
                            ap[st][c2*4+2], ap[st][c2*4+3], b2, b3);
                }
            }
        }
    }

    // normalize + write 'b n (h d)' as fp16
    #pragma unroll
    for (int st = 0; st < 2; st++) {
        float inv0 = 1.f / li[st][0], inv1 = 1.f / li[st][1];
        #pragma unroll
        for (int nt = 0; nt < 8; nt++) {
            int r = q0 + st * 64 + m0 + g;
            int c = hc + nt * 8 + 2 * qd;
            *(__half2*)(out + (size_t)((size_t)b * SEQ + r) * DMODEL + c) =
                __floats2half2_rn(o[st][nt][0] * inv0, o[st][nt][1] * inv0);
            *(__half2*)(out + (size_t)((size_t)b * SEQ + r + 8) * DMODEL + c) =
                __floats2half2_rn(o[st][nt][2] * inv1, o[st][nt][3] * inv1);
        }
    }
}

// ---------------------------------------------------------------------------
extern "C" void kernel_launch(void* const* d_in, const int* in_sizes, int n_in,
                              void* d_out, int out_size) {
    const float* x     = (const float*)d_in[0];
    const float* W_qkv = (const float*)d_in[1];
    const float* W_out = (const float*)d_in[2];
    const float* b_out = (const float*)d_in[3];
    float* out = (float*)d_out;

    __half *xh, *wqh, *woh, *qkv, *attn;
    cudaGetSymbolAddress((void**)&xh,   g_xh);
    cudaGetSymbolAddress((void**)&wqh,  g_wqh);
    cudaGetSymbolAddress((void**)&woh,  g_woh);
    cudaGetSymbolAddress((void**)&qkv,  g_qkv);
    cudaGetSymbolAddress((void**)&attn, g_attn);

    cudaFuncSetAttribute(flash_f16,
                         cudaFuncAttributeMaxDynamicSharedMemorySize,
                         FLASH_SMEM_BYTES);

    const int M = BATCH * SEQ;  // 8192
    const int NX = M * DMODEL, NWQ = DMODEL * QKVW, NWO = DMODEL * DMODEL;

    // 0) fp16 pre-conversion
    f32_to_f16<<<NX  / 1024, 256>>>(x,     xh,  NX);
    f32_to_f16<<<NWQ / 1024, 256>>>(W_qkv, wqh, NWQ);
    f32_to_f16<<<NWO / 1024, 256>>>(W_out, woh, NWO);

    // 1) qkv = x @ W_qkv  (fp16 out)
    gemm_f16<<<dim3(QKVW / BN, M / BM), 256>>>(
        xh, wqh, nullptr, qkv, M, QKVW, DMODEL, 1);

    // 2) attention (fp16 out)
    flash_f16<<<dim3(SEQ / QT, HEADS, BATCH), 128, FLASH_SMEM_BYTES>>>(
        qkv, attn);

    // 3) out = attn @ W_out + b_out  (fp32 out)
    gemm_f16<<<dim3(DMODEL / BN, M / BM), 256>>>(
        attn, woh, b_out, out, M, DMODEL, DMODEL, 0);
}